// round 12
// baseline (speedup 1.0000x reference)
#include <cuda_runtime.h>
#include <cuda_bf16.h>
#include <math.h>
#include <stdint.h>

#define B_N    8192
#define K_N    512
#define D_N    2048
#define Q_N    8
#define LOG2PI 1.8378770664093453f
#define EPSC   1e-5f

// ---------------- scratch (static __device__, no allocation) ----------------
__device__ __nv_bfloat16 g_XB[(size_t)B_N * D_N];   // X in bf16
__device__ __nv_bfloat16 g_WB[(size_t)4608 * D_N];  // [512 pm | 4096 pi*dv] x D, bf16
__device__ float         g_T [(size_t)B_N * K_N];   // t1[b][k]
__device__ __nv_bfloat16 g_V [(size_t)B_N * 4096];  // vtilde GEMM out, bf16
__device__ float  g_r[B_N];
__device__ float  g_Sacc[K_N * 4 * 56];             // per-chunk: 36 S + 8 wm + 8 ns + 1 mm
__device__ float  g_Lp[K_N * 48];                   // [0..35] sqrt(.5)*Linv*al_col | 8 wm | off
__device__ float  g_logdetM[K_N];
__device__ float  g_mumu[K_N];
__device__ double g_acc;

__device__ __forceinline__ float softplusf(float x) {
    return x > 20.0f ? x : log1pf(expf(x));
}
__device__ __forceinline__ uint32_t smem_u32(const void* p) {
    uint32_t a;
    asm("{ .reg .u64 t; cvta.to.shared.u64 t, %1; cvt.u32.u64 %0, t; }" : "=r"(a) : "l"(p));
    return a;
}
__device__ __forceinline__ void cp_async16(uint32_t saddr, const void* gaddr) {
    asm volatile("cp.async.cg.shared.global [%0], [%1], 16;" :: "r"(saddr), "l"(gaddr));
}
__device__ __forceinline__ float warp_sum(float v) {
#pragma unroll
    for (int o = 16; o; o >>= 1) v += __shfl_xor_sync(0xffffffffu, v, o);
    return v;
}

// ---------------- X -> bf16 + r[b]; psi computed locally in smem ------------
__global__ void k_cvt(const float* __restrict__ x,
                      const float* __restrict__ psi_rho, int b0) {
    __shared__ float s_pinv[D_N];
    int tid = threadIdx.x;
    for (int d = tid; d < D_N; d += 256)
        s_pinv[d] = 1.0f / (softplusf(psi_rho[d]) + EPSC);
    __syncthreads();

    int warp = tid >> 5, lane = tid & 31;
    int b = b0 + blockIdx.x * 8 + warp;
    const float* xb = x + (size_t)b * D_N;
    __nv_bfloat16* ob = g_XB + (size_t)b * D_N;
    float r = 0.0f;
    for (int d = lane * 4; d < D_N; d += 128) {
        float4 xv = *(const float4*)(xb + d);
        float4 pv = *(const float4*)(s_pinv + d);
        r += xv.x * xv.x * pv.x + xv.y * xv.y * pv.y
           + xv.z * xv.z * pv.z + xv.w * xv.w * pv.w;
        __nv_bfloat162 h0 = __float22bfloat162_rn(make_float2(xv.x, xv.y));
        __nv_bfloat162 h1 = __float22bfloat162_rn(make_float2(xv.z, xv.w));
        uint2 hb;
        hb.x = *(uint32_t*)&h0; hb.y = *(uint32_t*)&h1;
        *(uint2*)(ob + d) = hb;
    }
    r = warp_sum(r);
    if (lane == 0) g_r[b] = r;
}

// ---------------- pB: per-k stats + Wcat writes; local psi chunk ------------
__global__ void pB(const float* __restrict__ dir_raw,
                   const float* __restrict__ mu,
                   const float* __restrict__ psi_rho) {
    int k = blockIdx.y, chunk = blockIdx.x, tid = threadIdx.x, lane = tid & 31;
    __shared__ float s_acc[53];
    __shared__ float s_pinv[512];
    int d0 = chunk * 512;
    if (tid < 53) s_acc[tid] = 0.0f;
    for (int i = tid; i < 512; i += 256)
        s_pinv[i] = 1.0f / (softplusf(psi_rho[d0 + i]) + EPSC);
    __syncthreads();

    const float* dirk = dir_raw + (size_t)k * D_N * Q_N;
    const float* muk  = mu + (size_t)k * D_N;

    float S[36], wm[8], ns[8], mm = 0.0f;
#pragma unroll
    for (int i = 0; i < 36; i++) S[i] = 0.0f;
#pragma unroll
    for (int i = 0; i < 8; i++) { wm[i] = 0.0f; ns[i] = 0.0f; }

#pragma unroll
    for (int it = 0; it < 2; it++) {
        int dl = tid + it * 256;
        int d  = d0 + dl;
        float dv[8];
        float4 a  = *(const float4*)(dirk + (size_t)d * 8);
        float4 b4 = *(const float4*)(dirk + (size_t)d * 8 + 4);
        dv[0] = a.x; dv[1] = a.y; dv[2] = a.z; dv[3] = a.w;
        dv[4] = b4.x; dv[5] = b4.y; dv[6] = b4.z; dv[7] = b4.w;
        float pi = s_pinv[dl];
        float m  = muk[d];
        float pim = pi * m;
        mm += m * pim;
        int idx = 0;
#pragma unroll
        for (int i = 0; i < 8; i++) {
            float pdi = pi * dv[i];
            wm[i] += m * pdi;
            ns[i] += dv[i] * dv[i];
#pragma unroll
            for (int j = 0; j <= i; j++) S[idx++] += pdi * dv[j];
        }
        g_WB[(size_t)k * D_N + d] = __float2bfloat16(pim);
#pragma unroll
        for (int j = 0; j < 8; j++)
            g_WB[(size_t)(K_N + k * 8 + j) * D_N + d] = __float2bfloat16(pi * dv[j]);
    }
#pragma unroll
    for (int i = 0; i < 36; i++) {
        S[i] = warp_sum(S[i]);
        if (lane == 0) atomicAdd(&s_acc[i], S[i]);
    }
#pragma unroll
    for (int j = 0; j < 8; j++) {
        wm[j] = warp_sum(wm[j]);
        if (lane == 0) atomicAdd(&s_acc[36 + j], wm[j]);
        ns[j] = warp_sum(ns[j]);
        if (lane == 0) atomicAdd(&s_acc[44 + j], ns[j]);
    }
    mm = warp_sum(mm);
    if (lane == 0) atomicAdd(&s_acc[52], mm);
    __syncthreads();
    if (tid < 53) g_Sacc[(size_t)(k * 4 + chunk) * 56 + tid] = s_acc[tid];
}

// ---------------- bf16 MMA GEMM: 6-stage, 1 barrier per 2 kb (UNCHANGED) ----
#define BK       32
#define KBLOCKS  (D_N / BK)      // 64
#define STAGES   6
#define TILE_A   8192
#define TILE_B   8192
#define TILE_AB  (TILE_A + TILE_B)
#define GEMM_SMEM (STAGES * TILE_AB)   // 96 KB

__global__ void __launch_bounds__(256, 2) k_mma_gemm() {
    extern __shared__ __align__(128) char smem[];
    const int tid  = threadIdx.x;
    const int wid  = tid >> 5;
    const int lane = tid & 31;
    const int warp_m = wid & 1;
    const int warp_n = wid >> 1;
    const int bx = blockIdx.x;
    const int by = blockIdx.y;

    const uint32_t sbase = smem_u32(smem);
    const __nv_bfloat16* Ag = g_XB + (size_t)(by * 128) * D_N;
    const __nv_bfloat16* Bg = g_WB + (size_t)(bx * 128) * D_N;

    auto load_stage = [&](int s, int kb) {
        uint32_t aB = sbase + s * TILE_AB;
        uint32_t bB = aB + TILE_A;
#pragma unroll
        for (int i = 0; i < 2; i++) {
            int id  = tid + i * 256;
            int row = id >> 2;
            int ch  = id & 3;
            int sw  = ch ^ ((row >> 1) & 3);
            cp_async16(aB + row * 64 + sw * 16, Ag + (size_t)row * D_N + kb * BK + ch * 8);
            cp_async16(bB + row * 64 + sw * 16, Bg + (size_t)row * D_N + kb * BK + ch * 8);
        }
        asm volatile("cp.async.commit_group;");
    };

    float acc[4][4][4];
#pragma unroll
    for (int mi = 0; mi < 4; mi++)
#pragma unroll
        for (int ni = 0; ni < 4; ni++)
#pragma unroll
            for (int j = 0; j < 4; j++) acc[mi][ni][j] = 0.0f;

    auto compute_kb = [&](int kb) {
        uint32_t aB = sbase + (kb % STAGES) * TILE_AB;
        uint32_t bB = aB + TILE_A;
#pragma unroll
        for (int ks = 0; ks < 2; ks++) {
            uint32_t a[4][4], b[4][2];
#pragma unroll
            for (int mi = 0; mi < 4; mi++) {
                int r  = warp_m * 64 + mi * 16 + (lane & 15);
                int ch = ks * 2 + (lane >> 4);
                uint32_t ad = aB + r * 64 + ((ch ^ ((r >> 1) & 3)) << 4);
                asm volatile("ldmatrix.sync.aligned.m8n8.x4.shared.b16 {%0,%1,%2,%3}, [%4];"
                             : "=r"(a[mi][0]), "=r"(a[mi][1]), "=r"(a[mi][2]), "=r"(a[mi][3])
                             : "r"(ad));
            }
#pragma unroll
            for (int p = 0; p < 2; p++) {
                int g  = lane >> 3, rl = lane & 7;
                int r  = warp_n * 32 + p * 16 + (g >> 1) * 8 + rl;
                int ch = ks * 2 + (g & 1);
                uint32_t bd = bB + r * 64 + ((ch ^ ((r >> 1) & 3)) << 4);
                asm volatile("ldmatrix.sync.aligned.m8n8.x4.shared.b16 {%0,%1,%2,%3}, [%4];"
                             : "=r"(b[2 * p][0]), "=r"(b[2 * p][1]),
                               "=r"(b[2 * p + 1][0]), "=r"(b[2 * p + 1][1])
                             : "r"(bd));
            }
#pragma unroll
            for (int mi = 0; mi < 4; mi++)
#pragma unroll
                for (int ni = 0; ni < 4; ni++) {
                    asm volatile(
                        "mma.sync.aligned.m16n8k16.row.col.f32.bf16.bf16.f32 "
                        "{%0,%1,%2,%3}, {%4,%5,%6,%7}, {%8,%9}, {%0,%1,%2,%3};"
                        : "+f"(acc[mi][ni][0]), "+f"(acc[mi][ni][1]),
                          "+f"(acc[mi][ni][2]), "+f"(acc[mi][ni][3])
                        : "r"(a[mi][0]), "r"(a[mi][1]), "r"(a[mi][2]), "r"(a[mi][3]),
                          "r"(b[ni][0]), "r"(b[ni][1]));
                }
        }
    };

    load_stage(0, 0);
    load_stage(1, 1);
    load_stage(2, 2);
    load_stage(3, 3);

    for (int kb = 0; kb < KBLOCKS; kb += 2) {
        if (kb + 2 < KBLOCKS) asm volatile("cp.async.wait_group 2;");
        else                  asm volatile("cp.async.wait_group 0;");
        __syncthreads();
        if (kb + 4 < KBLOCKS) load_stage((kb + 4) % STAGES, kb + 4);
        if (kb + 5 < KBLOCKS) load_stage((kb + 5) % STAGES, kb + 5);
        compute_kb(kb);
        compute_kb(kb + 1);
    }

    const int gq = lane >> 2;
    const int tg = lane & 3;

    if (bx < 4) {
#pragma unroll
        for (int mi = 0; mi < 4; mi++) {
            int r0 = by * 128 + warp_m * 64 + mi * 16 + gq;
            int r1 = r0 + 8;
#pragma unroll
            for (int ni = 0; ni < 4; ni++) {
                int col = bx * 128 + warp_n * 32 + ni * 8 + tg * 2;
                *(float2*)&g_T[(size_t)r0 * K_N + col] = make_float2(acc[mi][ni][0], acc[mi][ni][1]);
                *(float2*)&g_T[(size_t)r1 * K_N + col] = make_float2(acc[mi][ni][2], acc[mi][ni][3]);
            }
        }
    } else {
#pragma unroll
        for (int mi = 0; mi < 4; mi++) {
            int r0 = by * 128 + warp_m * 64 + mi * 16 + gq;
            int r1 = r0 + 8;
#pragma unroll
            for (int ni = 0; ni < 4; ni++) {
                int col = (bx - 4) * 128 + warp_n * 32 + ni * 8 + tg * 2;
                __nv_bfloat162 lo = __float22bfloat162_rn(make_float2(acc[mi][ni][0], acc[mi][ni][1]));
                __nv_bfloat162 hi = __float22bfloat162_rn(make_float2(acc[mi][ni][2], acc[mi][ni][3]));
                *(__nv_bfloat162*)&g_V[(size_t)r0 * 4096 + col] = lo;
                *(__nv_bfloat162*)&g_V[(size_t)r1 * 4096 + col] = hi;
            }
        }
    }
}

// ---------------- pC: reduce chunks, alpha, Cholesky -> packed Lp -----------
__global__ void pC(const float* __restrict__ scale_rho) {
    int k = blockIdx.x * 128 + threadIdx.x;
    if (k >= K_N) return;
    float buf[53];
    for (int i = 0; i < 53; i++) {
        float s = 0.0f;
        for (int c = 0; c < 4; c++) s += g_Sacc[(size_t)(k * 4 + c) * 56 + i];
        buf[i] = s;
    }
    float al[8];
#pragma unroll
    for (int j = 0; j < 8; j++) {
        float sp = softplusf(scale_rho[k * 8 + j]);
        al[j] = sp / fmaxf(sqrtf(buf[44 + j]), EPSC);
    }

    float Mm[8][8];
    int idx = 0;
    for (int i = 0; i < 8; i++)
        for (int j = 0; j <= i; j++)
            Mm[i][j] = al[i] * al[j] * buf[idx++] + (i == j ? 1.0f : 0.0f);
    for (int i = 0; i < 8; i++) {
        for (int j = 0; j <= i; j++) {
            float s = Mm[i][j];
            for (int p = 0; p < j; p++) s -= Mm[i][p] * Mm[j][p];
            if (i == j) Mm[i][i] = sqrtf(s);
            else        Mm[i][j] = s / Mm[j][j];
        }
    }
    float ld = 0.0f;
    for (int i = 0; i < 8; i++) ld += logf(Mm[i][i]);
    g_logdetM[k] = 2.0f * ld;
    g_mumu[k]    = buf[52];
    for (int j = 0; j < 8; j++) g_Lp[k * 48 + 36 + j] = buf[36 + j];

    float Li[8][8];
    for (int i = 0; i < 8; i++)
        for (int j = 0; j < 8; j++) Li[i][j] = 0.0f;
    for (int c = 0; c < 8; c++) {
        for (int i = c; i < 8; i++) {
            float s = (i == c) ? 1.0f : 0.0f;
            for (int p = c; p < i; p++) s -= Mm[i][p] * Li[p][c];
            Li[i][c] = s / Mm[i][i];
        }
    }
    idx = 0;
    for (int i = 0; i < 8; i++)
        for (int j = 0; j <= i; j++)
            g_Lp[k * 48 + idx++] = 0.70710678118654752f * Li[i][j] * al[j];
}

__global__ void k_init() { g_acc = 0.0; }

// ---------------- per-k offset -> g_Lp[44]; logdetPsi computed here ---------
__global__ void k_off(const float* __restrict__ pi_logits,
                      const float* __restrict__ psi_rho) {
    __shared__ float buf[512];
    __shared__ float buf2[512];
    int t = threadIdx.x;
    float l = 0.0f;
    for (int d = t; d < D_N; d += 512)
        l += logf(softplusf(psi_rho[d]) + EPSC);
    buf2[t] = l;
    float v = pi_logits[t];
    buf[t] = v;
    __syncthreads();
    for (int s = 256; s > 0; s >>= 1) {
        if (t < s) {
            buf[t]  = fmaxf(buf[t], buf[t + s]);
            buf2[t] += buf2[t + s];
        }
        __syncthreads();
    }
    float mx = buf[0];
    float logdetPsi = buf2[0];
    __syncthreads();
    buf[t] = expf(v - mx);
    __syncthreads();
    for (int s = 256; s > 0; s >>= 1) {
        if (t < s) buf[t] += buf[t + s];
        __syncthreads();
    }
    float lse = logf(buf[0]) + mx;
    g_Lp[t * 48 + 44] = -0.5f * ((float)D_N * LOG2PI + logdetPsi + g_logdetM[t] + g_mumu[t])
                        + v - lse;
}

// ---------------- fused e1+e2: quad (Cholesky form) + logsumexp + NLL -------
__global__ void __launch_bounds__(256) k_e2() {
    __shared__ float sL[64 * 49];
    int tid = threadIdx.x, warp = tid >> 5, lane = tid & 31;
    int b0 = blockIdx.x * 16 + warp * 2;
    int b1 = b0 + 1;
    const __nv_bfloat16* vr0 = g_V + (size_t)b0 * 4096;
    const __nv_bfloat16* vr1 = g_V + (size_t)b1 * 4096;
    const float* tr0 = g_T + (size_t)b0 * K_N;
    const float* tr1 = g_T + (size_t)b1 * K_N;

    float m0 = -1e30f, s0 = 0.0f, m1 = -1e30f, s1 = 0.0f;
    for (int ch = 0; ch < 8; ch++) {
        int k0 = ch * 64;
        for (int t = tid; t < 64 * 48; t += 256) {
            int kk = t / 48, c = t - kk * 48;
            sL[kk * 49 + c] = g_Lp[(size_t)(k0 + kk) * 48 + c];
        }
        __syncthreads();
#pragma unroll
        for (int half = 0; half < 2; half++) {
            int kl = half * 32 + lane;
            int k  = k0 + kl;
            const float* P = &sL[kl * 49];
#pragma unroll
            for (int bb = 0; bb < 2; bb++) {
                const __nv_bfloat16* vrow = bb ? vr1 : vr0;
                const float*          trow = bb ? tr1 : tr0;
                uint4 raw = *(const uint4*)(vrow + (size_t)k * 8);
                float v[8];
                {
                    float2 f0 = __bfloat1622float2(*(__nv_bfloat162*)&raw.x);
                    float2 f1 = __bfloat1622float2(*(__nv_bfloat162*)&raw.y);
                    float2 f2 = __bfloat1622float2(*(__nv_bfloat162*)&raw.z);
                    float2 f3 = __bfloat1622float2(*(__nv_bfloat162*)&raw.w);
                    v[0] = f0.x; v[1] = f0.y; v[2] = f1.x; v[3] = f1.y;
                    v[4] = f2.x; v[5] = f2.y; v[6] = f3.x; v[7] = f3.y;
                }
#pragma unroll
                for (int j = 0; j < 8; j++) v[j] -= P[36 + j];
                float q = 0.0f;
                int idx = 0;
#pragma unroll
                for (int i = 0; i < 8; i++) {
                    float y = 0.0f;
#pragma unroll
                    for (int j = 0; j <= i; j++) y += P[idx++] * v[j];
                    q += y * y;
                }
                float val = trow[k] + P[44] + q;
                if (bb == 0) {
                    if (val > m0) { s0 = s0 * __expf(m0 - val) + 1.0f; m0 = val; }
                    else          { s0 += __expf(val - m0); }
                } else {
                    if (val > m1) { s1 = s1 * __expf(m1 - val) + 1.0f; m1 = val; }
                    else          { s1 += __expf(val - m1); }
                }
            }
        }
        __syncthreads();
    }
#pragma unroll
    for (int o = 16; o; o >>= 1) {
        float mo = __shfl_xor_sync(0xffffffffu, m0, o);
        float so = __shfl_xor_sync(0xffffffffu, s0, o);
        float M = fmaxf(m0, mo);
        s0 = s0 * __expf(m0 - M) + so * __expf(mo - M);
        m0 = M;
        mo = __shfl_xor_sync(0xffffffffu, m1, o);
        so = __shfl_xor_sync(0xffffffffu, s1, o);
        M = fmaxf(m1, mo);
        s1 = s1 * __expf(m1 - M) + so * __expf(mo - M);
        m1 = M;
    }
    if (lane == 0) {
        float lp = (__logf(s0) + m0 - 0.5f * g_r[b0]) + (__logf(s1) + m1 - 0.5f * g_r[b1]);
        atomicAdd(&g_acc, (double)(-lp));
    }
}

__global__ void k_fin(float* out) { out[0] = (float)(g_acc * (1.0 / (double)B_N)); }

// ---------------- launch (pB is 4th => gets profiled) ----------------
extern "C" void kernel_launch(void* const* d_in, const int* in_sizes, int n_in,
                              void* d_out, int out_size) {
    const float* x         = (const float*)d_in[0];
    const float* mu        = (const float*)d_in[1];
    const float* dir_raw   = (const float*)d_in[2];
    const float* scale_rho = (const float*)d_in[3];
    const float* psi_rho   = (const float*)d_in[4];
    const float* pi_logits = (const float*)d_in[5];
    float* out = (float*)d_out;

    cudaFuncSetAttribute(k_mma_gemm, cudaFuncAttributeMaxDynamicSharedMemorySize, GEMM_SMEM);

    k_cvt<<<B_N / 16, 256>>>(x, psi_rho, 0);                // 1
    k_cvt<<<B_N / 16, 256>>>(x, psi_rho, B_N / 2);          // 2
    k_init<<<1, 1>>>();                                     // 3
    pB<<<dim3(4, K_N), 256>>>(dir_raw, mu, psi_rho);        // 4  <- profiled
    dim3 gg(36, 64);
    k_mma_gemm<<<gg, 256, GEMM_SMEM>>>();                   // 5
    pC<<<4, 128>>>(scale_rho);                              // 6
    k_off<<<1, 512>>>(pi_logits, psi_rho);                  // 7
    k_e2<<<B_N / 16, 256>>>();                              // 8
    k_fin<<<1, 1>>>(out);                                   // 9
}

// round 13
// speedup vs baseline: 1.0642x; 1.0642x over previous
#include <cuda_runtime.h>
#include <cuda_bf16.h>
#include <math.h>
#include <stdint.h>

#define B_N    8192
#define K_N    512
#define D_N    2048
#define Q_N    8
#define LOG2PI 1.8378770664093453f
#define EPSC   1e-5f

// ---------------- scratch (static __device__, no allocation) ----------------
__device__ __nv_bfloat16 g_XB[(size_t)B_N * D_N];   // X in bf16
__device__ __nv_bfloat16 g_WB[(size_t)4608 * D_N];  // [512 pm | 4096 pi*dv] x D, bf16
__device__ float         g_T [(size_t)B_N * K_N];   // t1[b][k]
__device__ __nv_bfloat16 g_V [(size_t)B_N * 4096];  // vtilde GEMM out, bf16
__device__ float  g_psi_inv[D_N];
__device__ float  g_logdetPsi;
__device__ float  g_r[B_N];
__device__ float  g_Sacc[K_N * 4 * 56];             // per-chunk: 36 S + 8 wm + 8 ns + 1 mm
__device__ float  g_Lp[K_N * 48];                   // [0..35] sqrt(.5)*Linv*al_col | 8 wm | off
__device__ float  g_logdetM[K_N];
__device__ float  g_mumu[K_N];
__device__ double g_acc;

__device__ __forceinline__ float softplusf(float x) {
    return x > 20.0f ? x : log1pf(expf(x));
}
__device__ __forceinline__ uint32_t smem_u32(const void* p) {
    uint32_t a;
    asm("{ .reg .u64 t; cvta.to.shared.u64 t, %1; cvt.u32.u64 %0, t; }" : "=r"(a) : "l"(p));
    return a;
}
__device__ __forceinline__ void cp_async16(uint32_t saddr, const void* gaddr) {
    asm volatile("cp.async.cg.shared.global [%0], [%1], 16;" :: "r"(saddr), "l"(gaddr));
}
__device__ __forceinline__ float warp_sum(float v) {
#pragma unroll
    for (int o = 16; o; o >>= 1) v += __shfl_xor_sync(0xffffffffu, v, o);
    return v;
}

// ---------------- psi precompute ----------------
__global__ void k_psi(const float* __restrict__ psi_rho) {
    __shared__ float ssum;
    int tid = threadIdx.x;
    if (tid == 0) ssum = 0.0f;
    __syncthreads();
    float l = 0.0f;
    for (int d = tid; d < D_N; d += 1024) {
        float p = softplusf(psi_rho[d]) + EPSC;
        g_psi_inv[d] = 1.0f / p;
        l += logf(p);
    }
    l = warp_sum(l);
    if ((tid & 31) == 0) atomicAdd(&ssum, l);
    __syncthreads();
    if (tid == 0) g_logdetPsi = ssum;
}

// ---------------- X -> bf16 + r[b] (warp per row) ----------------
__global__ void k_cvt(const float* __restrict__ x) {
    int warp = threadIdx.x >> 5, lane = threadIdx.x & 31;
    int b = blockIdx.x * 8 + warp;
    const float* xb = x + (size_t)b * D_N;
    __nv_bfloat16* ob = g_XB + (size_t)b * D_N;
    float r = 0.0f;
    for (int d = lane * 4; d < D_N; d += 128) {
        float4 xv = *(const float4*)(xb + d);
        float4 pv = *(const float4*)(g_psi_inv + d);
        r += xv.x * xv.x * pv.x + xv.y * xv.y * pv.y
           + xv.z * xv.z * pv.z + xv.w * xv.w * pv.w;
        __nv_bfloat162 h0 = __float22bfloat162_rn(make_float2(xv.x, xv.y));
        __nv_bfloat162 h1 = __float22bfloat162_rn(make_float2(xv.z, xv.w));
        uint2 hb;
        hb.x = *(uint32_t*)&h0; hb.y = *(uint32_t*)&h1;
        *(uint2*)(ob + d) = hb;
    }
    r = warp_sum(r);
    if (lane == 0) g_r[b] = r;
}

// ---------------- pB: per-k stats (S, wm, ns, mm) + Wcat writes -------------
__global__ void pB(const float* __restrict__ dir_raw,
                   const float* __restrict__ mu) {
    int k = blockIdx.y, chunk = blockIdx.x, tid = threadIdx.x, lane = tid & 31;
    __shared__ float s_acc[53];
    if (tid < 53) s_acc[tid] = 0.0f;
    __syncthreads();

    const float* dirk = dir_raw + (size_t)k * D_N * Q_N;
    const float* muk  = mu + (size_t)k * D_N;

    float S[36], wm[8], ns[8], mm = 0.0f;
#pragma unroll
    for (int i = 0; i < 36; i++) S[i] = 0.0f;
#pragma unroll
    for (int i = 0; i < 8; i++) { wm[i] = 0.0f; ns[i] = 0.0f; }

    int d0 = chunk * 512;
#pragma unroll
    for (int it = 0; it < 2; it++) {
        int d = d0 + tid + it * 256;
        float dv[8];
        float4 a  = *(const float4*)(dirk + (size_t)d * 8);
        float4 b4 = *(const float4*)(dirk + (size_t)d * 8 + 4);
        dv[0] = a.x; dv[1] = a.y; dv[2] = a.z; dv[3] = a.w;
        dv[4] = b4.x; dv[5] = b4.y; dv[6] = b4.z; dv[7] = b4.w;
        float pi = g_psi_inv[d];
        float m  = muk[d];
        float pim = pi * m;
        mm += m * pim;
        int idx = 0;
#pragma unroll
        for (int i = 0; i < 8; i++) {
            float pdi = pi * dv[i];
            wm[i] += m * pdi;
            ns[i] += dv[i] * dv[i];
#pragma unroll
            for (int j = 0; j <= i; j++) S[idx++] += pdi * dv[j];
        }
        g_WB[(size_t)k * D_N + d] = __float2bfloat16(pim);
#pragma unroll
        for (int j = 0; j < 8; j++)
            g_WB[(size_t)(K_N + k * 8 + j) * D_N + d] = __float2bfloat16(pi * dv[j]);
    }
#pragma unroll
    for (int i = 0; i < 36; i++) {
        S[i] = warp_sum(S[i]);
        if (lane == 0) atomicAdd(&s_acc[i], S[i]);
    }
#pragma unroll
    for (int j = 0; j < 8; j++) {
        wm[j] = warp_sum(wm[j]);
        if (lane == 0) atomicAdd(&s_acc[36 + j], wm[j]);
        ns[j] = warp_sum(ns[j]);
        if (lane == 0) atomicAdd(&s_acc[44 + j], ns[j]);
    }
    mm = warp_sum(mm);
    if (lane == 0) atomicAdd(&s_acc[52], mm);
    __syncthreads();
    if (tid < 53) g_Sacc[(size_t)(k * 4 + chunk) * 56 + tid] = s_acc[tid];
}

// ---------------- bf16 MMA GEMM: 128 threads, 4 warps of 64x64 --------------
// CTA tile 128x128, BK=32, 4 stages, occ 3 -> halves cross-warp LDSM traffic.
#define BK       32
#define KBLOCKS  (D_N / BK)      // 64
#define STAGES   4
#define TILE_A   8192
#define TILE_B   8192
#define TILE_AB  (TILE_A + TILE_B)
#define GEMM_SMEM (STAGES * TILE_AB)   // 64 KB

__global__ void __launch_bounds__(128, 3) k_mma_gemm() {
    extern __shared__ __align__(128) char smem[];
    const int tid  = threadIdx.x;
    const int wid  = tid >> 5;
    const int lane = tid & 31;
    const int warp_m = wid & 1;    // 2 x 64 rows
    const int warp_n = wid >> 1;   // 2 x 64 cols
    const int bx = blockIdx.x;     // 0..35 (bx<4 -> t1 region, else v region)
    const int by = blockIdx.y;     // 0..63

    const uint32_t sbase = smem_u32(smem);
    const __nv_bfloat16* Ag = g_XB + (size_t)(by * 128) * D_N;
    const __nv_bfloat16* Bg = g_WB + (size_t)(bx * 128) * D_N;

    auto load_stage = [&](int s, int kb) {
        uint32_t aB = sbase + s * TILE_AB;
        uint32_t bB = aB + TILE_A;
#pragma unroll
        for (int i = 0; i < 4; i++) {
            int id  = tid + i * 128;     // 0..511
            int row = id >> 2;
            int ch  = id & 3;
            int sw  = ch ^ ((row >> 1) & 3);
            cp_async16(aB + row * 64 + sw * 16, Ag + (size_t)row * D_N + kb * BK + ch * 8);
            cp_async16(bB + row * 64 + sw * 16, Bg + (size_t)row * D_N + kb * BK + ch * 8);
        }
        asm volatile("cp.async.commit_group;");
    };

    float acc[4][8][4];
#pragma unroll
    for (int mi = 0; mi < 4; mi++)
#pragma unroll
        for (int ni = 0; ni < 8; ni++)
#pragma unroll
            for (int j = 0; j < 4; j++) acc[mi][ni][j] = 0.0f;

    load_stage(0, 0);
    load_stage(1, 1);
    load_stage(2, 2);

    for (int kb = 0; kb < KBLOCKS; kb++) {
        if (kb + 2 < KBLOCKS)       asm volatile("cp.async.wait_group 2;");
        else if (kb + 2 == KBLOCKS) asm volatile("cp.async.wait_group 1;");
        else                        asm volatile("cp.async.wait_group 0;");
        __syncthreads();
        if (kb + 3 < KBLOCKS) load_stage((kb + 3) & 3, kb + 3);
        uint32_t aB = sbase + (kb & 3) * TILE_AB;
        uint32_t bB = aB + TILE_A;
#pragma unroll
        for (int ks = 0; ks < 2; ks++) {
            uint32_t a[4][4];
#pragma unroll
            for (int mi = 0; mi < 4; mi++) {
                int r  = warp_m * 64 + mi * 16 + (lane & 15);
                int ch = ks * 2 + (lane >> 4);
                uint32_t ad = aB + r * 64 + ((ch ^ ((r >> 1) & 3)) << 4);
                asm volatile("ldmatrix.sync.aligned.m8n8.x4.shared.b16 {%0,%1,%2,%3}, [%4];"
                             : "=r"(a[mi][0]), "=r"(a[mi][1]), "=r"(a[mi][2]), "=r"(a[mi][3])
                             : "r"(ad));
            }
#pragma unroll
            for (int p = 0; p < 4; p++) {       // B loaded per-p, consumed immediately
                uint32_t b0[2], b1[2];
                int g  = lane >> 3, rl = lane & 7;
                int r  = warp_n * 64 + p * 16 + (g >> 1) * 8 + rl;
                int ch = ks * 2 + (g & 1);
                uint32_t bd = bB + r * 64 + ((ch ^ ((r >> 1) & 3)) << 4);
                asm volatile("ldmatrix.sync.aligned.m8n8.x4.shared.b16 {%0,%1,%2,%3}, [%4];"
                             : "=r"(b0[0]), "=r"(b0[1]), "=r"(b1[0]), "=r"(b1[1])
                             : "r"(bd));
#pragma unroll
                for (int mi = 0; mi < 4; mi++) {
                    asm volatile(
                        "mma.sync.aligned.m16n8k16.row.col.f32.bf16.bf16.f32 "
                        "{%0,%1,%2,%3}, {%4,%5,%6,%7}, {%8,%9}, {%0,%1,%2,%3};"
                        : "+f"(acc[mi][2*p][0]), "+f"(acc[mi][2*p][1]),
                          "+f"(acc[mi][2*p][2]), "+f"(acc[mi][2*p][3])
                        : "r"(a[mi][0]), "r"(a[mi][1]), "r"(a[mi][2]), "r"(a[mi][3]),
                          "r"(b0[0]), "r"(b0[1]));
                    asm volatile(
                        "mma.sync.aligned.m16n8k16.row.col.f32.bf16.bf16.f32 "
                        "{%0,%1,%2,%3}, {%4,%5,%6,%7}, {%8,%9}, {%0,%1,%2,%3};"
                        : "+f"(acc[mi][2*p+1][0]), "+f"(acc[mi][2*p+1][1]),
                          "+f"(acc[mi][2*p+1][2]), "+f"(acc[mi][2*p+1][3])
                        : "r"(a[mi][0]), "r"(a[mi][1]), "r"(a[mi][2]), "r"(a[mi][3]),
                          "r"(b1[0]), "r"(b1[1]));
                }
            }
        }
    }

    const int gq = lane >> 2;
    const int tg = lane & 3;

    if (bx < 4) {
#pragma unroll
        for (int mi = 0; mi < 4; mi++) {
            int r0 = by * 128 + warp_m * 64 + mi * 16 + gq;
            int r1 = r0 + 8;
#pragma unroll
            for (int ni = 0; ni < 8; ni++) {
                int col = bx * 128 + warp_n * 64 + ni * 8 + tg * 2;
                *(float2*)&g_T[(size_t)r0 * K_N + col] = make_float2(acc[mi][ni][0], acc[mi][ni][1]);
                *(float2*)&g_T[(size_t)r1 * K_N + col] = make_float2(acc[mi][ni][2], acc[mi][ni][3]);
            }
        }
    } else {
#pragma unroll
        for (int mi = 0; mi < 4; mi++) {
            int r0 = by * 128 + warp_m * 64 + mi * 16 + gq;
            int r1 = r0 + 8;
#pragma unroll
            for (int ni = 0; ni < 8; ni++) {
                int col = (bx - 4) * 128 + warp_n * 64 + ni * 8 + tg * 2;
                __nv_bfloat162 lo = __float22bfloat162_rn(make_float2(acc[mi][ni][0], acc[mi][ni][1]));
                __nv_bfloat162 hi = __float22bfloat162_rn(make_float2(acc[mi][ni][2], acc[mi][ni][3]));
                *(__nv_bfloat162*)&g_V[(size_t)r0 * 4096 + col] = lo;
                *(__nv_bfloat162*)&g_V[(size_t)r1 * 4096 + col] = hi;
            }
        }
    }
}

// ---------------- pC: reduce chunks, alpha, Cholesky -> packed Lp -----------
__global__ void pC(const float* __restrict__ scale_rho) {
    int k = blockIdx.x * 128 + threadIdx.x;
    if (k >= K_N) return;
    float buf[53];
    for (int i = 0; i < 53; i++) {
        float s = 0.0f;
        for (int c = 0; c < 4; c++) s += g_Sacc[(size_t)(k * 4 + c) * 56 + i];
        buf[i] = s;
    }
    float al[8];
#pragma unroll
    for (int j = 0; j < 8; j++) {
        float sp = softplusf(scale_rho[k * 8 + j]);
        al[j] = sp / fmaxf(sqrtf(buf[44 + j]), EPSC);
    }

    float Mm[8][8];
    int idx = 0;
    for (int i = 0; i < 8; i++)
        for (int j = 0; j <= i; j++)
            Mm[i][j] = al[i] * al[j] * buf[idx++] + (i == j ? 1.0f : 0.0f);
    for (int i = 0; i < 8; i++) {
        for (int j = 0; j <= i; j++) {
            float s = Mm[i][j];
            for (int p = 0; p < j; p++) s -= Mm[i][p] * Mm[j][p];
            if (i == j) Mm[i][i] = sqrtf(s);
            else        Mm[i][j] = s / Mm[j][j];
        }
    }
    float ld = 0.0f;
    for (int i = 0; i < 8; i++) ld += logf(Mm[i][i]);
    g_logdetM[k] = 2.0f * ld;
    g_mumu[k]    = buf[52];
    for (int j = 0; j < 8; j++) g_Lp[k * 48 + 36 + j] = buf[36 + j];

    float Li[8][8];
    for (int i = 0; i < 8; i++)
        for (int j = 0; j < 8; j++) Li[i][j] = 0.0f;
    for (int c = 0; c < 8; c++) {
        for (int i = c; i < 8; i++) {
            float s = (i == c) ? 1.0f : 0.0f;
            for (int p = c; p < i; p++) s -= Mm[i][p] * Li[p][c];
            Li[i][c] = s / Mm[i][i];
        }
    }
    idx = 0;
    for (int i = 0; i < 8; i++)
        for (int j = 0; j <= i; j++)
            g_Lp[k * 48 + idx++] = 0.70710678118654752f * Li[i][j] * al[j];
}

__global__ void k_init() { g_acc = 0.0; }

// ---------------- per-k offset -> g_Lp[44] ----------------
__global__ void k_off(const float* __restrict__ pi_logits) {
    __shared__ float buf[512];
    int t = threadIdx.x;
    float v = pi_logits[t];
    buf[t] = v;
    __syncthreads();
    for (int s = 256; s > 0; s >>= 1) {
        if (t < s) buf[t] = fmaxf(buf[t], buf[t + s]);
        __syncthreads();
    }
    float mx = buf[0];
    __syncthreads();
    buf[t] = expf(v - mx);
    __syncthreads();
    for (int s = 256; s > 0; s >>= 1) {
        if (t < s) buf[t] += buf[t + s];
        __syncthreads();
    }
    float lse = logf(buf[0]) + mx;
    g_Lp[t * 48 + 44] = -0.5f * ((float)D_N * LOG2PI + g_logdetPsi + g_logdetM[t] + g_mumu[t])
                        + v - lse;
}

// ---------------- fused e1+e2: quad (Cholesky form) + logsumexp + NLL -------
__global__ void __launch_bounds__(256) k_e2() {
    __shared__ float sL[64 * 49];
    int tid = threadIdx.x, warp = tid >> 5, lane = tid & 31;
    int b0 = blockIdx.x * 16 + warp * 2;
    int b1 = b0 + 1;
    const __nv_bfloat16* vr0 = g_V + (size_t)b0 * 4096;
    const __nv_bfloat16* vr1 = g_V + (size_t)b1 * 4096;
    const float* tr0 = g_T + (size_t)b0 * K_N;
    const float* tr1 = g_T + (size_t)b1 * K_N;

    float m0 = -1e30f, s0 = 0.0f, m1 = -1e30f, s1 = 0.0f;
    for (int ch = 0; ch < 8; ch++) {
        int k0 = ch * 64;
        for (int t = tid; t < 64 * 48; t += 256) {
            int kk = t / 48, c = t - kk * 48;
            sL[kk * 49 + c] = g_Lp[(size_t)(k0 + kk) * 48 + c];
        }
        __syncthreads();
#pragma unroll
        for (int half = 0; half < 2; half++) {
            int kl = half * 32 + lane;
            int k  = k0 + kl;
            const float* P = &sL[kl * 49];
#pragma unroll
            for (int bb = 0; bb < 2; bb++) {
                const __nv_bfloat16* vrow = bb ? vr1 : vr0;
                const float*          trow = bb ? tr1 : tr0;
                uint4 raw = *(const uint4*)(vrow + (size_t)k * 8);
                float v[8];
                {
                    float2 f0 = __bfloat1622float2(*(__nv_bfloat162*)&raw.x);
                    float2 f1 = __bfloat1622float2(*(__nv_bfloat162*)&raw.y);
                    float2 f2 = __bfloat1622float2(*(__nv_bfloat162*)&raw.z);
                    float2 f3 = __bfloat1622float2(*(__nv_bfloat162*)&raw.w);
                    v[0] = f0.x; v[1] = f0.y; v[2] = f1.x; v[3] = f1.y;
                    v[4] = f2.x; v[5] = f2.y; v[6] = f3.x; v[7] = f3.y;
                }
#pragma unroll
                for (int j = 0; j < 8; j++) v[j] -= P[36 + j];
                float q = 0.0f;
                int idx = 0;
#pragma unroll
                for (int i = 0; i < 8; i++) {
                    float y = 0.0f;
#pragma unroll
                    for (int j = 0; j <= i; j++) y += P[idx++] * v[j];
                    q += y * y;
                }
                float val = trow[k] + P[44] + q;
                if (bb == 0) {
                    if (val > m0) { s0 = s0 * __expf(m0 - val) + 1.0f; m0 = val; }
                    else          { s0 += __expf(val - m0); }
                } else {
                    if (val > m1) { s1 = s1 * __expf(m1 - val) + 1.0f; m1 = val; }
                    else          { s1 += __expf(val - m1); }
                }
            }
        }
        __syncthreads();
    }
#pragma unroll
    for (int o = 16; o; o >>= 1) {
        float mo = __shfl_xor_sync(0xffffffffu, m0, o);
        float so = __shfl_xor_sync(0xffffffffu, s0, o);
        float M = fmaxf(m0, mo);
        s0 = s0 * __expf(m0 - M) + so * __expf(mo - M);
        m0 = M;
        mo = __shfl_xor_sync(0xffffffffu, m1, o);
        so = __shfl_xor_sync(0xffffffffu, s1, o);
        M = fmaxf(m1, mo);
        s1 = s1 * __expf(m1 - M) + so * __expf(mo - M);
        m1 = M;
    }
    if (lane == 0) {
        float lp = (__logf(s0) + m0 - 0.5f * g_r[b0]) + (__logf(s1) + m1 - 0.5f * g_r[b1]);
        atomicAdd(&g_acc, (double)(-lp));
    }
}

__global__ void k_fin(float* out) { out[0] = (float)(g_acc * (1.0 / (double)B_N)); }

// ---------------- launch (GEMM is 4th => gets profiled) ----------------
extern "C" void kernel_launch(void* const* d_in, const int* in_sizes, int n_in,
                              void* d_out, int out_size) {
    const float* x         = (const float*)d_in[0];
    const float* mu        = (const float*)d_in[1];
    const float* dir_raw   = (const float*)d_in[2];
    const float* scale_rho = (const float*)d_in[3];
    const float* psi_rho   = (const float*)d_in[4];
    const float* pi_logits = (const float*)d_in[5];
    float* out = (float*)d_out;

    cudaFuncSetAttribute(k_mma_gemm, cudaFuncAttributeMaxDynamicSharedMemorySize, GEMM_SMEM);

    k_psi<<<1, 1024>>>(psi_rho);                            // 1
    k_cvt<<<B_N / 8, 256>>>(x);                             // 2
    pB<<<dim3(4, K_N), 256>>>(dir_raw, mu);                 // 3
    dim3 gg(36, 64);
    k_mma_gemm<<<gg, 128, GEMM_SMEM>>>();                   // 4  <- profiled
    pC<<<4, 128>>>(scale_rho);                              // 5
    k_init<<<1, 1>>>();                                     // 6
    k_off<<<1, 512>>>(pi_logits);                           // 7
    k_e2<<<B_N / 16, 256>>>();                              // 8
    k_fin<<<1, 1>>>(out);                                   // 9
}

// round 14
// speedup vs baseline: 1.1330x; 1.0646x over previous
#include <cuda_runtime.h>
#include <cuda_bf16.h>
#include <math.h>
#include <stdint.h>

#define B_N    8192
#define K_N    512
#define D_N    2048
#define Q_N    8
#define LOG2PI 1.8378770664093453f
#define EPSC   1e-5f

// ---------------- scratch (static __device__, no allocation) ----------------
__device__ __nv_bfloat16 g_XB[(size_t)B_N * D_N];   // X in bf16
__device__ __nv_bfloat16 g_WB[(size_t)4608 * D_N];  // [512 pm | 4096 pi*dv] x D, bf16
__device__ float         g_T [(size_t)B_N * K_N];   // t1[b][k]
__device__ __nv_bfloat16 g_V [(size_t)B_N * 4096];  // vtilde GEMM out, bf16
__device__ float  g_psi_inv[D_N];
__device__ float  g_logdetPsi;
__device__ float  g_r[B_N];
__device__ float  g_Sacc[K_N * 4 * 56];             // per-chunk: 36 S + 8 wm + 8 ns + 1 mm
__device__ float  g_Lp[K_N * 48];                   // [0..35] sqrt(.5)*Linv*al_col | 8 wm | off
__device__ float  g_logdetM[K_N];
__device__ float  g_mumu[K_N];
__device__ double g_acc;

__device__ __forceinline__ float softplusf(float x) {
    return x > 20.0f ? x : log1pf(expf(x));
}
__device__ __forceinline__ uint32_t smem_u32(const void* p) {
    uint32_t a;
    asm("{ .reg .u64 t; cvta.to.shared.u64 t, %1; cvt.u32.u64 %0, t; }" : "=r"(a) : "l"(p));
    return a;
}
__device__ __forceinline__ void cp_async16(uint32_t saddr, const void* gaddr) {
    asm volatile("cp.async.cg.shared.global [%0], [%1], 16;" :: "r"(saddr), "l"(gaddr));
}
__device__ __forceinline__ float warp_sum(float v) {
#pragma unroll
    for (int o = 16; o; o >>= 1) v += __shfl_xor_sync(0xffffffffu, v, o);
    return v;
}

// ---------------- psi precompute ----------------
__global__ void k_psi(const float* __restrict__ psi_rho) {
    __shared__ float ssum;
    int tid = threadIdx.x;
    if (tid == 0) ssum = 0.0f;
    __syncthreads();
    float l = 0.0f;
    for (int d = tid; d < D_N; d += 1024) {
        float p = softplusf(psi_rho[d]) + EPSC;
        g_psi_inv[d] = 1.0f / p;
        l += logf(p);
    }
    l = warp_sum(l);
    if ((tid & 31) == 0) atomicAdd(&ssum, l);
    __syncthreads();
    if (tid == 0) g_logdetPsi = ssum;
}

// ---------------- X -> bf16 + r[b] (warp per row) ----------------
__global__ void k_cvt(const float* __restrict__ x) {
    int warp = threadIdx.x >> 5, lane = threadIdx.x & 31;
    int b = blockIdx.x * 8 + warp;
    const float* xb = x + (size_t)b * D_N;
    __nv_bfloat16* ob = g_XB + (size_t)b * D_N;
    float r = 0.0f;
    for (int d = lane * 4; d < D_N; d += 128) {
        float4 xv = *(const float4*)(xb + d);
        float4 pv = *(const float4*)(g_psi_inv + d);
        r += xv.x * xv.x * pv.x + xv.y * xv.y * pv.y
           + xv.z * xv.z * pv.z + xv.w * xv.w * pv.w;
        __nv_bfloat162 h0 = __float22bfloat162_rn(make_float2(xv.x, xv.y));
        __nv_bfloat162 h1 = __float22bfloat162_rn(make_float2(xv.z, xv.w));
        uint2 hb;
        hb.x = *(uint32_t*)&h0; hb.y = *(uint32_t*)&h1;
        *(uint2*)(ob + d) = hb;
    }
    r = warp_sum(r);
    if (lane == 0) g_r[b] = r;
}

// ---------------- pB: per-k stats (S, wm, ns, mm) + Wcat writes -------------
__global__ void pB(const float* __restrict__ dir_raw,
                   const float* __restrict__ mu) {
    int k = blockIdx.y, chunk = blockIdx.x, tid = threadIdx.x, lane = tid & 31;
    __shared__ float s_acc[53];
    if (tid < 53) s_acc[tid] = 0.0f;
    __syncthreads();

    const float* dirk = dir_raw + (size_t)k * D_N * Q_N;
    const float* muk  = mu + (size_t)k * D_N;

    float S[36], wm[8], ns[8], mm = 0.0f;
#pragma unroll
    for (int i = 0; i < 36; i++) S[i] = 0.0f;
#pragma unroll
    for (int i = 0; i < 8; i++) { wm[i] = 0.0f; ns[i] = 0.0f; }

    int d0 = chunk * 512;
#pragma unroll
    for (int it = 0; it < 2; it++) {
        int d = d0 + tid + it * 256;
        float dv[8];
        float4 a  = *(const float4*)(dirk + (size_t)d * 8);
        float4 b4 = *(const float4*)(dirk + (size_t)d * 8 + 4);
        dv[0] = a.x; dv[1] = a.y; dv[2] = a.z; dv[3] = a.w;
        dv[4] = b4.x; dv[5] = b4.y; dv[6] = b4.z; dv[7] = b4.w;
        float pi = g_psi_inv[d];
        float m  = muk[d];
        float pim = pi * m;
        mm += m * pim;
        int idx = 0;
#pragma unroll
        for (int i = 0; i < 8; i++) {
            float pdi = pi * dv[i];
            wm[i] += m * pdi;
            ns[i] += dv[i] * dv[i];
#pragma unroll
            for (int j = 0; j <= i; j++) S[idx++] += pdi * dv[j];
        }
        g_WB[(size_t)k * D_N + d] = __float2bfloat16(pim);
#pragma unroll
        for (int j = 0; j < 8; j++)
            g_WB[(size_t)(K_N + k * 8 + j) * D_N + d] = __float2bfloat16(pi * dv[j]);
    }
#pragma unroll
    for (int i = 0; i < 36; i++) {
        S[i] = warp_sum(S[i]);
        if (lane == 0) atomicAdd(&s_acc[i], S[i]);
    }
#pragma unroll
    for (int j = 0; j < 8; j++) {
        wm[j] = warp_sum(wm[j]);
        if (lane == 0) atomicAdd(&s_acc[36 + j], wm[j]);
        ns[j] = warp_sum(ns[j]);
        if (lane == 0) atomicAdd(&s_acc[44 + j], ns[j]);
    }
    mm = warp_sum(mm);
    if (lane == 0) atomicAdd(&s_acc[52], mm);
    __syncthreads();
    if (tid < 53) g_Sacc[(size_t)(k * 4 + chunk) * 56 + tid] = s_acc[tid];
}

// ---------------- bf16 MMA GEMM: 128 threads, 4 warps of 64x64 --------------
#define BK       32
#define KBLOCKS  (D_N / BK)      // 64
#define STAGES   4
#define TILE_A   8192
#define TILE_B   8192
#define TILE_AB  (TILE_A + TILE_B)
#define GEMM_SMEM (STAGES * TILE_AB)   // 64 KB

__global__ void __launch_bounds__(128, 3) k_mma_gemm() {
    extern __shared__ __align__(128) char smem[];
    const int tid  = threadIdx.x;
    const int wid  = tid >> 5;
    const int lane = tid & 31;
    const int warp_m = wid & 1;    // 2 x 64 rows
    const int warp_n = wid >> 1;   // 2 x 64 cols
    const int bx = blockIdx.x;     // 0..35 (bx<4 -> t1 region, else v region)
    const int by = blockIdx.y;     // 0..63

    const uint32_t sbase = smem_u32(smem);
    const __nv_bfloat16* Ag = g_XB + (size_t)(by * 128) * D_N;
    const __nv_bfloat16* Bg = g_WB + (size_t)(bx * 128) * D_N;

    auto load_stage = [&](int s, int kb) {
        uint32_t aB = sbase + s * TILE_AB;
        uint32_t bB = aB + TILE_A;
#pragma unroll
        for (int i = 0; i < 4; i++) {
            int id  = tid + i * 128;     // 0..511
            int row = id >> 2;
            int ch  = id & 3;
            int sw  = ch ^ ((row >> 1) & 3);
            cp_async16(aB + row * 64 + sw * 16, Ag + (size_t)row * D_N + kb * BK + ch * 8);
            cp_async16(bB + row * 64 + sw * 16, Bg + (size_t)row * D_N + kb * BK + ch * 8);
        }
        asm volatile("cp.async.commit_group;");
    };

    float acc[4][8][4];
#pragma unroll
    for (int mi = 0; mi < 4; mi++)
#pragma unroll
        for (int ni = 0; ni < 8; ni++)
#pragma unroll
            for (int j = 0; j < 4; j++) acc[mi][ni][j] = 0.0f;

    load_stage(0, 0);
    load_stage(1, 1);
    load_stage(2, 2);

    for (int kb = 0; kb < KBLOCKS; kb++) {
        if (kb + 2 < KBLOCKS)       asm volatile("cp.async.wait_group 2;");
        else if (kb + 2 == KBLOCKS) asm volatile("cp.async.wait_group 1;");
        else                        asm volatile("cp.async.wait_group 0;");
        __syncthreads();
        if (kb + 3 < KBLOCKS) load_stage((kb + 3) & 3, kb + 3);
        uint32_t aB = sbase + (kb & 3) * TILE_AB;
        uint32_t bB = aB + TILE_A;
#pragma unroll
        for (int ks = 0; ks < 2; ks++) {
            uint32_t a[4][4];
#pragma unroll
            for (int mi = 0; mi < 4; mi++) {
                int r  = warp_m * 64 + mi * 16 + (lane & 15);
                int ch = ks * 2 + (lane >> 4);
                uint32_t ad = aB + r * 64 + ((ch ^ ((r >> 1) & 3)) << 4);
                asm volatile("ldmatrix.sync.aligned.m8n8.x4.shared.b16 {%0,%1,%2,%3}, [%4];"
                             : "=r"(a[mi][0]), "=r"(a[mi][1]), "=r"(a[mi][2]), "=r"(a[mi][3])
                             : "r"(ad));
            }
#pragma unroll
            for (int p = 0; p < 4; p++) {
                uint32_t b0[2], b1[2];
                int g  = lane >> 3, rl = lane & 7;
                int r  = warp_n * 64 + p * 16 + (g >> 1) * 8 + rl;
                int ch = ks * 2 + (g & 1);
                uint32_t bd = bB + r * 64 + ((ch ^ ((r >> 1) & 3)) << 4);
                asm volatile("ldmatrix.sync.aligned.m8n8.x4.shared.b16 {%0,%1,%2,%3}, [%4];"
                             : "=r"(b0[0]), "=r"(b0[1]), "=r"(b1[0]), "=r"(b1[1])
                             : "r"(bd));
#pragma unroll
                for (int mi = 0; mi < 4; mi++) {
                    asm volatile(
                        "mma.sync.aligned.m16n8k16.row.col.f32.bf16.bf16.f32 "
                        "{%0,%1,%2,%3}, {%4,%5,%6,%7}, {%8,%9}, {%0,%1,%2,%3};"
                        : "+f"(acc[mi][2*p][0]), "+f"(acc[mi][2*p][1]),
                          "+f"(acc[mi][2*p][2]), "+f"(acc[mi][2*p][3])
                        : "r"(a[mi][0]), "r"(a[mi][1]), "r"(a[mi][2]), "r"(a[mi][3]),
                          "r"(b0[0]), "r"(b0[1]));
                    asm volatile(
                        "mma.sync.aligned.m16n8k16.row.col.f32.bf16.bf16.f32 "
                        "{%0,%1,%2,%3}, {%4,%5,%6,%7}, {%8,%9}, {%0,%1,%2,%3};"
                        : "+f"(acc[mi][2*p+1][0]), "+f"(acc[mi][2*p+1][1]),
                          "+f"(acc[mi][2*p+1][2]), "+f"(acc[mi][2*p+1][3])
                        : "r"(a[mi][0]), "r"(a[mi][1]), "r"(a[mi][2]), "r"(a[mi][3]),
                          "r"(b1[0]), "r"(b1[1]));
                }
            }
        }
    }

    const int gq = lane >> 2;
    const int tg = lane & 3;

    if (bx < 4) {
#pragma unroll
        for (int mi = 0; mi < 4; mi++) {
            int r0 = by * 128 + warp_m * 64 + mi * 16 + gq;
            int r1 = r0 + 8;
#pragma unroll
            for (int ni = 0; ni < 8; ni++) {
                int col = bx * 128 + warp_n * 64 + ni * 8 + tg * 2;
                *(float2*)&g_T[(size_t)r0 * K_N + col] = make_float2(acc[mi][ni][0], acc[mi][ni][1]);
                *(float2*)&g_T[(size_t)r1 * K_N + col] = make_float2(acc[mi][ni][2], acc[mi][ni][3]);
            }
        }
    } else {
#pragma unroll
        for (int mi = 0; mi < 4; mi++) {
            int r0 = by * 128 + warp_m * 64 + mi * 16 + gq;
            int r1 = r0 + 8;
#pragma unroll
            for (int ni = 0; ni < 8; ni++) {
                int col = (bx - 4) * 128 + warp_n * 64 + ni * 8 + tg * 2;
                __nv_bfloat162 lo = __float22bfloat162_rn(make_float2(acc[mi][ni][0], acc[mi][ni][1]));
                __nv_bfloat162 hi = __float22bfloat162_rn(make_float2(acc[mi][ni][2], acc[mi][ni][3]));
                *(__nv_bfloat162*)&g_V[(size_t)r0 * 4096 + col] = lo;
                *(__nv_bfloat162*)&g_V[(size_t)r1 * 4096 + col] = hi;
            }
        }
    }
}

// ---------------- pC: reduce chunks, alpha, Cholesky -> packed Lp -----------
__global__ void pC(const float* __restrict__ scale_rho) {
    int k = blockIdx.x * 128 + threadIdx.x;
    if (k >= K_N) return;
    float buf[53];
    for (int i = 0; i < 53; i++) {
        float s = 0.0f;
        for (int c = 0; c < 4; c++) s += g_Sacc[(size_t)(k * 4 + c) * 56 + i];
        buf[i] = s;
    }
    float al[8];
#pragma unroll
    for (int j = 0; j < 8; j++) {
        float sp = softplusf(scale_rho[k * 8 + j]);
        al[j] = sp / fmaxf(sqrtf(buf[44 + j]), EPSC);
    }

    float Mm[8][8];
    int idx = 0;
    for (int i = 0; i < 8; i++)
        for (int j = 0; j <= i; j++)
            Mm[i][j] = al[i] * al[j] * buf[idx++] + (i == j ? 1.0f : 0.0f);
    for (int i = 0; i < 8; i++) {
        for (int j = 0; j <= i; j++) {
            float s = Mm[i][j];
            for (int p = 0; p < j; p++) s -= Mm[i][p] * Mm[j][p];
            if (i == j) Mm[i][i] = sqrtf(s);
            else        Mm[i][j] = s / Mm[j][j];
        }
    }
    float ld = 0.0f;
    for (int i = 0; i < 8; i++) ld += logf(Mm[i][i]);
    g_logdetM[k] = 2.0f * ld;
    g_mumu[k]    = buf[52];
    for (int j = 0; j < 8; j++) g_Lp[k * 48 + 36 + j] = buf[36 + j];

    float Li[8][8];
    for (int i = 0; i < 8; i++)
        for (int j = 0; j < 8; j++) Li[i][j] = 0.0f;
    for (int c = 0; c < 8; c++) {
        for (int i = c; i < 8; i++) {
            float s = (i == c) ? 1.0f : 0.0f;
            for (int p = c; p < i; p++) s -= Mm[i][p] * Li[p][c];
            Li[i][c] = s / Mm[i][i];
        }
    }
    idx = 0;
    for (int i = 0; i < 8; i++)
        for (int j = 0; j <= i; j++)
            g_Lp[k * 48 + idx++] = 0.70710678118654752f * Li[i][j] * al[j];
}

__global__ void k_init() { g_acc = 0.0; }

// ---------------- per-k offset -> g_Lp[44] ----------------
__global__ void k_off(const float* __restrict__ pi_logits) {
    __shared__ float buf[512];
    int t = threadIdx.x;
    float v = pi_logits[t];
    buf[t] = v;
    __syncthreads();
    for (int s = 256; s > 0; s >>= 1) {
        if (t < s) buf[t] = fmaxf(buf[t], buf[t + s]);
        __syncthreads();
    }
    float mx = buf[0];
    __syncthreads();
    buf[t] = expf(v - mx);
    __syncthreads();
    for (int s = 256; s > 0; s >>= 1) {
        if (t < s) buf[t] += buf[t + s];
        __syncthreads();
    }
    float lse = logf(buf[0]) + mx;
    g_Lp[t * 48 + 44] = -0.5f * ((float)D_N * LOG2PI + g_logdetPsi + g_logdetM[t] + g_mumu[t])
                        + v - lse;
}

// ---------------- fused e1+e2: quad (Cholesky form) + logsumexp + NLL -------
__global__ void __launch_bounds__(256) k_e2() {
    __shared__ float sL[64 * 49];
    int tid = threadIdx.x, warp = tid >> 5, lane = tid & 31;
    int b0 = blockIdx.x * 16 + warp * 2;
    int b1 = b0 + 1;
    const __nv_bfloat16* vr0 = g_V + (size_t)b0 * 4096;
    const __nv_bfloat16* vr1 = g_V + (size_t)b1 * 4096;
    const float* tr0 = g_T + (size_t)b0 * K_N;
    const float* tr1 = g_T + (size_t)b1 * K_N;

    float m0 = -1e30f, s0 = 0.0f, m1 = -1e30f, s1 = 0.0f;
    for (int ch = 0; ch < 8; ch++) {
        int k0 = ch * 64;
        for (int t = tid; t < 64 * 48; t += 256) {
            int kk = t / 48, c = t - kk * 48;
            sL[kk * 49 + c] = g_Lp[(size_t)(k0 + kk) * 48 + c];
        }
        __syncthreads();
#pragma unroll
        for (int half = 0; half < 2; half++) {
            int kl = half * 32 + lane;
            int k  = k0 + kl;
            const float* P = &sL[kl * 49];
#pragma unroll
            for (int bb = 0; bb < 2; bb++) {
                const __nv_bfloat16* vrow = bb ? vr1 : vr0;
                const float*          trow = bb ? tr1 : tr0;
                uint4 raw = *(const uint4*)(vrow + (size_t)k * 8);
                float v[8];
                {
                    float2 f0 = __bfloat1622float2(*(__nv_bfloat162*)&raw.x);
                    float2 f1 = __bfloat1622float2(*(__nv_bfloat162*)&raw.y);
                    float2 f2 = __bfloat1622float2(*(__nv_bfloat162*)&raw.z);
                    float2 f3 = __bfloat1622float2(*(__nv_bfloat162*)&raw.w);
                    v[0] = f0.x; v[1] = f0.y; v[2] = f1.x; v[3] = f1.y;
                    v[4] = f2.x; v[5] = f2.y; v[6] = f3.x; v[7] = f3.y;
                }
#pragma unroll
                for (int j = 0; j < 8; j++) v[j] -= P[36 + j];
                float q = 0.0f;
                int idx = 0;
#pragma unroll
                for (int i = 0; i < 8; i++) {
                    float y = 0.0f;
#pragma unroll
                    for (int j = 0; j <= i; j++) y += P[idx++] * v[j];
                    q += y * y;
                }
                float val = trow[k] + P[44] + q;
                if (bb == 0) {
                    if (val > m0) { s0 = s0 * __expf(m0 - val) + 1.0f; m0 = val; }
                    else          { s0 += __expf(val - m0); }
                } else {
                    if (val > m1) { s1 = s1 * __expf(m1 - val) + 1.0f; m1 = val; }
                    else          { s1 += __expf(val - m1); }
                }
            }
        }
        __syncthreads();
    }
#pragma unroll
    for (int o = 16; o; o >>= 1) {
        float mo = __shfl_xor_sync(0xffffffffu, m0, o);
        float so = __shfl_xor_sync(0xffffffffu, s0, o);
        float M = fmaxf(m0, mo);
        s0 = s0 * __expf(m0 - M) + so * __expf(mo - M);
        m0 = M;
        mo = __shfl_xor_sync(0xffffffffu, m1, o);
        so = __shfl_xor_sync(0xffffffffu, s1, o);
        M = fmaxf(m1, mo);
        s1 = s1 * __expf(m1 - M) + so * __expf(mo - M);
        m1 = M;
    }
    if (lane == 0) {
        float lp = (__logf(s0) + m0 - 0.5f * g_r[b0]) + (__logf(s1) + m1 - 0.5f * g_r[b1]);
        atomicAdd(&g_acc, (double)(-lp));
    }
}

__global__ void k_fin(float* out) { out[0] = (float)(g_acc * (1.0 / (double)B_N)); }

// ---------------- launch: multi-stream fork/join for overlap ----------------
extern "C" void kernel_launch(void* const* d_in, const int* in_sizes, int n_in,
                              void* d_out, int out_size) {
    const float* x         = (const float*)d_in[0];
    const float* mu        = (const float*)d_in[1];
    const float* dir_raw   = (const float*)d_in[2];
    const float* scale_rho = (const float*)d_in[3];
    const float* psi_rho   = (const float*)d_in[4];
    const float* pi_logits = (const float*)d_in[5];
    float* out = (float*)d_out;

    static cudaStream_t s_aux = nullptr;
    static cudaEvent_t ev_fork1, ev_join1, ev_fork2, ev_join2;
    if (!s_aux) {
        cudaStreamCreateWithFlags(&s_aux, cudaStreamNonBlocking);
        cudaEventCreateWithFlags(&ev_fork1, cudaEventDisableTiming);
        cudaEventCreateWithFlags(&ev_join1, cudaEventDisableTiming);
        cudaEventCreateWithFlags(&ev_fork2, cudaEventDisableTiming);
        cudaEventCreateWithFlags(&ev_join2, cudaEventDisableTiming);
        cudaFuncSetAttribute(k_mma_gemm, cudaFuncAttributeMaxDynamicSharedMemorySize, GEMM_SMEM);
    }

    // main: psi, then fork
    k_psi<<<1, 1024>>>(psi_rho);
    cudaEventRecord(ev_fork1, 0);
    cudaStreamWaitEvent(s_aux, ev_fork1, 0);

    // aux: X conversion (|| with pB on main)
    k_cvt<<<B_N / 8, 256, 0, s_aux>>>(x);
    cudaEventRecord(ev_join1, s_aux);

    // main: W construction
    pB<<<dim3(4, K_N), 256>>>(dir_raw, mu);

    // fork 2: pC/init/off chain on aux (|| with GEMM on main)
    cudaEventRecord(ev_fork2, 0);
    cudaStreamWaitEvent(s_aux, ev_fork2, 0);   // aux now ordered after k_cvt AND pB
    pC<<<4, 128, 0, s_aux>>>(scale_rho);
    k_init<<<1, 1, 0, s_aux>>>();
    k_off<<<1, 512, 0, s_aux>>>(pi_logits);
    cudaEventRecord(ev_join2, s_aux);

    // main: GEMM (needs g_XB from aux + g_WB from pB)
    cudaStreamWaitEvent(0, ev_join1, 0);
    dim3 gg(36, 64);
    k_mma_gemm<<<gg, 128, GEMM_SMEM>>>();

    // main: epilogue (needs GEMM + aux chain)
    cudaStreamWaitEvent(0, ev_join2, 0);
    k_e2<<<B_N / 16, 256>>>();
    k_fin<<<1, 1>>>(out);
}

// round 15
// speedup vs baseline: 1.1376x; 1.0041x over previous
#include <cuda_runtime.h>
#include <cuda_bf16.h>
#include <math.h>
#include <stdint.h>

#define B_N    8192
#define K_N    512
#define D_N    2048
#define Q_N    8
#define LOG2PI 1.8378770664093453f
#define EPSC   1e-5f

// ---------------- scratch (static __device__, no allocation) ----------------
__device__ __nv_bfloat16 g_XB[(size_t)B_N * D_N];   // X in bf16
__device__ __nv_bfloat16 g_WB[(size_t)4608 * D_N];  // [512 pm | 4096 pi*dv] x D, bf16
__device__ float         g_T [(size_t)B_N * K_N];   // t1[b][k]
__device__ __nv_bfloat16 g_V [(size_t)B_N * 4096];  // vtilde GEMM out, bf16
__device__ float  g_psi_inv[D_N];
__device__ float  g_logdetPsi;
__device__ float  g_r[B_N];
__device__ float  g_Sacc[K_N * 4 * 56];             // per-chunk: 36 S + 8 wm + 8 ns + 1 mm
__device__ float  g_Lp[K_N * 48];                   // [0..35] sqrt(.5)*Linv*al_col | 8 wm | off
__device__ float  g_logdetM[K_N];
__device__ float  g_mumu[K_N];
__device__ double g_acc;

__device__ __forceinline__ float softplusf(float x) {
    return x > 20.0f ? x : log1pf(expf(x));
}
__device__ __forceinline__ uint32_t smem_u32(const void* p) {
    uint32_t a;
    asm("{ .reg .u64 t; cvta.to.shared.u64 t, %1; cvt.u32.u64 %0, t; }" : "=r"(a) : "l"(p));
    return a;
}
__device__ __forceinline__ void cp_async16(uint32_t saddr, const void* gaddr) {
    asm volatile("cp.async.cg.shared.global [%0], [%1], 16;" :: "r"(saddr), "l"(gaddr));
}
__device__ __forceinline__ float warp_sum(float v) {
#pragma unroll
    for (int o = 16; o; o >>= 1) v += __shfl_xor_sync(0xffffffffu, v, o);
    return v;
}

// ---------------- psi precompute ----------------
__global__ void k_psi(const float* __restrict__ psi_rho) {
    __shared__ float ssum;
    int tid = threadIdx.x;
    if (tid == 0) ssum = 0.0f;
    __syncthreads();
    float l = 0.0f;
    for (int d = tid; d < D_N; d += 1024) {
        float p = softplusf(psi_rho[d]) + EPSC;
        g_psi_inv[d] = 1.0f / p;
        l += logf(p);
    }
    l = warp_sum(l);
    if ((tid & 31) == 0) atomicAdd(&ssum, l);
    __syncthreads();
    if (tid == 0) g_logdetPsi = ssum;
}

// ---------------- X -> bf16 + r[b] (warp per row) ----------------
__global__ void k_cvt(const float* __restrict__ x) {
    int warp = threadIdx.x >> 5, lane = threadIdx.x & 31;
    int b = blockIdx.x * 8 + warp;
    const float* xb = x + (size_t)b * D_N;
    __nv_bfloat16* ob = g_XB + (size_t)b * D_N;
    float r = 0.0f;
    for (int d = lane * 4; d < D_N; d += 128) {
        float4 xv = *(const float4*)(xb + d);
        float4 pv = *(const float4*)(g_psi_inv + d);
        r += xv.x * xv.x * pv.x + xv.y * xv.y * pv.y
           + xv.z * xv.z * pv.z + xv.w * xv.w * pv.w;
        __nv_bfloat162 h0 = __float22bfloat162_rn(make_float2(xv.x, xv.y));
        __nv_bfloat162 h1 = __float22bfloat162_rn(make_float2(xv.z, xv.w));
        uint2 hb;
        hb.x = *(uint32_t*)&h0; hb.y = *(uint32_t*)&h1;
        *(uint2*)(ob + d) = hb;
    }
    r = warp_sum(r);
    if (lane == 0) g_r[b] = r;
}

// ---------------- pB: per-k stats (S, wm, ns, mm) + Wcat writes -------------
__global__ void pB(const float* __restrict__ dir_raw,
                   const float* __restrict__ mu) {
    int k = blockIdx.y, chunk = blockIdx.x, tid = threadIdx.x, lane = tid & 31;
    __shared__ float s_acc[53];
    if (tid < 53) s_acc[tid] = 0.0f;
    __syncthreads();

    const float* dirk = dir_raw + (size_t)k * D_N * Q_N;
    const float* muk  = mu + (size_t)k * D_N;

    float S[36], wm[8], ns[8], mm = 0.0f;
#pragma unroll
    for (int i = 0; i < 36; i++) S[i] = 0.0f;
#pragma unroll
    for (int i = 0; i < 8; i++) { wm[i] = 0.0f; ns[i] = 0.0f; }

    int d0 = chunk * 512;
#pragma unroll
    for (int it = 0; it < 2; it++) {
        int d = d0 + tid + it * 256;
        float dv[8];
        float4 a  = *(const float4*)(dirk + (size_t)d * 8);
        float4 b4 = *(const float4*)(dirk + (size_t)d * 8 + 4);
        dv[0] = a.x; dv[1] = a.y; dv[2] = a.z; dv[3] = a.w;
        dv[4] = b4.x; dv[5] = b4.y; dv[6] = b4.z; dv[7] = b4.w;
        float pi = g_psi_inv[d];
        float m  = muk[d];
        float pim = pi * m;
        mm += m * pim;
        int idx = 0;
#pragma unroll
        for (int i = 0; i < 8; i++) {
            float pdi = pi * dv[i];
            wm[i] += m * pdi;
            ns[i] += dv[i] * dv[i];
#pragma unroll
            for (int j = 0; j <= i; j++) S[idx++] += pdi * dv[j];
        }
        g_WB[(size_t)k * D_N + d] = __float2bfloat16(pim);
#pragma unroll
        for (int j = 0; j < 8; j++)
            g_WB[(size_t)(K_N + k * 8 + j) * D_N + d] = __float2bfloat16(pi * dv[j]);
    }
#pragma unroll
    for (int i = 0; i < 36; i++) {
        S[i] = warp_sum(S[i]);
        if (lane == 0) atomicAdd(&s_acc[i], S[i]);
    }
#pragma unroll
    for (int j = 0; j < 8; j++) {
        wm[j] = warp_sum(wm[j]);
        if (lane == 0) atomicAdd(&s_acc[36 + j], wm[j]);
        ns[j] = warp_sum(ns[j]);
        if (lane == 0) atomicAdd(&s_acc[44 + j], ns[j]);
    }
    mm = warp_sum(mm);
    if (lane == 0) atomicAdd(&s_acc[52], mm);
    __syncthreads();
    if (tid < 53) g_Sacc[(size_t)(k * 4 + chunk) * 56 + tid] = s_acc[tid];
}

// ---------------- bf16 MMA GEMM: 128 threads, 4 warps of 64x64 --------------
#define BK       32
#define KBLOCKS  (D_N / BK)      // 64
#define STAGES   4
#define TILE_A   8192
#define TILE_B   8192
#define TILE_AB  (TILE_A + TILE_B)
#define GEMM_SMEM (STAGES * TILE_AB)   // 64 KB

__global__ void __launch_bounds__(128, 3) k_mma_gemm() {
    extern __shared__ __align__(128) char smem[];
    const int tid  = threadIdx.x;
    const int wid  = tid >> 5;
    const int lane = tid & 31;
    const int warp_m = wid & 1;    // 2 x 64 rows
    const int warp_n = wid >> 1;   // 2 x 64 cols
    const int bx = blockIdx.x;     // 0..35 (bx<4 -> t1 region, else v region)
    const int by = blockIdx.y;     // 0..63

    const uint32_t sbase = smem_u32(smem);
    const __nv_bfloat16* Ag = g_XB + (size_t)(by * 128) * D_N;
    const __nv_bfloat16* Bg = g_WB + (size_t)(bx * 128) * D_N;

    auto load_stage = [&](int s, int kb) {
        uint32_t aB = sbase + s * TILE_AB;
        uint32_t bB = aB + TILE_A;
#pragma unroll
        for (int i = 0; i < 4; i++) {
            int id  = tid + i * 128;     // 0..511
            int row = id >> 2;
            int ch  = id & 3;
            int sw  = ch ^ ((row >> 1) & 3);
            cp_async16(aB + row * 64 + sw * 16, Ag + (size_t)row * D_N + kb * BK + ch * 8);
            cp_async16(bB + row * 64 + sw * 16, Bg + (size_t)row * D_N + kb * BK + ch * 8);
        }
        asm volatile("cp.async.commit_group;");
    };

    float acc[4][8][4];
#pragma unroll
    for (int mi = 0; mi < 4; mi++)
#pragma unroll
        for (int ni = 0; ni < 8; ni++)
#pragma unroll
            for (int j = 0; j < 4; j++) acc[mi][ni][j] = 0.0f;

    load_stage(0, 0);
    load_stage(1, 1);
    load_stage(2, 2);

    for (int kb = 0; kb < KBLOCKS; kb++) {
        if (kb + 2 < KBLOCKS)       asm volatile("cp.async.wait_group 2;");
        else if (kb + 2 == KBLOCKS) asm volatile("cp.async.wait_group 1;");
        else                        asm volatile("cp.async.wait_group 0;");
        __syncthreads();
        if (kb + 3 < KBLOCKS) load_stage((kb + 3) & 3, kb + 3);
        uint32_t aB = sbase + (kb & 3) * TILE_AB;
        uint32_t bB = aB + TILE_A;
#pragma unroll
        for (int ks = 0; ks < 2; ks++) {
            uint32_t a[4][4];
#pragma unroll
            for (int mi = 0; mi < 4; mi++) {
                int r  = warp_m * 64 + mi * 16 + (lane & 15);
                int ch = ks * 2 + (lane >> 4);
                uint32_t ad = aB + r * 64 + ((ch ^ ((r >> 1) & 3)) << 4);
                asm volatile("ldmatrix.sync.aligned.m8n8.x4.shared.b16 {%0,%1,%2,%3}, [%4];"
                             : "=r"(a[mi][0]), "=r"(a[mi][1]), "=r"(a[mi][2]), "=r"(a[mi][3])
                             : "r"(ad));
            }
#pragma unroll
            for (int p = 0; p < 4; p++) {
                uint32_t b0[2], b1[2];
                int g  = lane >> 3, rl = lane & 7;
                int r  = warp_n * 64 + p * 16 + (g >> 1) * 8 + rl;
                int ch = ks * 2 + (g & 1);
                uint32_t bd = bB + r * 64 + ((ch ^ ((r >> 1) & 3)) << 4);
                asm volatile("ldmatrix.sync.aligned.m8n8.x4.shared.b16 {%0,%1,%2,%3}, [%4];"
                             : "=r"(b0[0]), "=r"(b0[1]), "=r"(b1[0]), "=r"(b1[1])
                             : "r"(bd));
#pragma unroll
                for (int mi = 0; mi < 4; mi++) {
                    asm volatile(
                        "mma.sync.aligned.m16n8k16.row.col.f32.bf16.bf16.f32 "
                        "{%0,%1,%2,%3}, {%4,%5,%6,%7}, {%8,%9}, {%0,%1,%2,%3};"
                        : "+f"(acc[mi][2*p][0]), "+f"(acc[mi][2*p][1]),
                          "+f"(acc[mi][2*p][2]), "+f"(acc[mi][2*p][3])
                        : "r"(a[mi][0]), "r"(a[mi][1]), "r"(a[mi][2]), "r"(a[mi][3]),
                          "r"(b0[0]), "r"(b0[1]));
                    asm volatile(
                        "mma.sync.aligned.m16n8k16.row.col.f32.bf16.bf16.f32 "
                        "{%0,%1,%2,%3}, {%4,%5,%6,%7}, {%8,%9}, {%0,%1,%2,%3};"
                        : "+f"(acc[mi][2*p+1][0]), "+f"(acc[mi][2*p+1][1]),
                          "+f"(acc[mi][2*p+1][2]), "+f"(acc[mi][2*p+1][3])
                        : "r"(a[mi][0]), "r"(a[mi][1]), "r"(a[mi][2]), "r"(a[mi][3]),
                          "r"(b1[0]), "r"(b1[1]));
                }
            }
        }
    }

    const int gq = lane >> 2;
    const int tg = lane & 3;

    if (bx < 4) {
#pragma unroll
        for (int mi = 0; mi < 4; mi++) {
            int r0 = by * 128 + warp_m * 64 + mi * 16 + gq;
            int r1 = r0 + 8;
#pragma unroll
            for (int ni = 0; ni < 8; ni++) {
                int col = bx * 128 + warp_n * 64 + ni * 8 + tg * 2;
                *(float2*)&g_T[(size_t)r0 * K_N + col] = make_float2(acc[mi][ni][0], acc[mi][ni][1]);
                *(float2*)&g_T[(size_t)r1 * K_N + col] = make_float2(acc[mi][ni][2], acc[mi][ni][3]);
            }
        }
    } else {
#pragma unroll
        for (int mi = 0; mi < 4; mi++) {
            int r0 = by * 128 + warp_m * 64 + mi * 16 + gq;
            int r1 = r0 + 8;
#pragma unroll
            for (int ni = 0; ni < 8; ni++) {
                int col = (bx - 4) * 128 + warp_n * 64 + ni * 8 + tg * 2;
                __nv_bfloat162 lo = __float22bfloat162_rn(make_float2(acc[mi][ni][0], acc[mi][ni][1]));
                __nv_bfloat162 hi = __float22bfloat162_rn(make_float2(acc[mi][ni][2], acc[mi][ni][3]));
                *(__nv_bfloat162*)&g_V[(size_t)r0 * 4096 + col] = lo;
                *(__nv_bfloat162*)&g_V[(size_t)r1 * 4096 + col] = hi;
            }
        }
    }
}

// ---------------- pC: reduce chunks, alpha, Cholesky -> packed Lp -----------
__global__ void pC(const float* __restrict__ scale_rho) {
    int k = blockIdx.x * 128 + threadIdx.x;
    if (k >= K_N) return;
    float buf[53];
    for (int i = 0; i < 53; i++) {
        float s = 0.0f;
        for (int c = 0; c < 4; c++) s += g_Sacc[(size_t)(k * 4 + c) * 56 + i];
        buf[i] = s;
    }
    float al[8];
#pragma unroll
    for (int j = 0; j < 8; j++) {
        float sp = softplusf(scale_rho[k * 8 + j]);
        al[j] = sp / fmaxf(sqrtf(buf[44 + j]), EPSC);
    }

    float Mm[8][8];
    int idx = 0;
    for (int i = 0; i < 8; i++)
        for (int j = 0; j <= i; j++)
            Mm[i][j] = al[i] * al[j] * buf[idx++] + (i == j ? 1.0f : 0.0f);
    for (int i = 0; i < 8; i++) {
        for (int j = 0; j <= i; j++) {
            float s = Mm[i][j];
            for (int p = 0; p < j; p++) s -= Mm[i][p] * Mm[j][p];
            if (i == j) Mm[i][i] = sqrtf(s);
            else        Mm[i][j] = s / Mm[j][j];
        }
    }
    float ld = 0.0f;
    for (int i = 0; i < 8; i++) ld += logf(Mm[i][i]);
    g_logdetM[k] = 2.0f * ld;
    g_mumu[k]    = buf[52];
    for (int j = 0; j < 8; j++) g_Lp[k * 48 + 36 + j] = buf[36 + j];

    float Li[8][8];
    for (int i = 0; i < 8; i++)
        for (int j = 0; j < 8; j++) Li[i][j] = 0.0f;
    for (int c = 0; c < 8; c++) {
        for (int i = c; i < 8; i++) {
            float s = (i == c) ? 1.0f : 0.0f;
            for (int p = c; p < i; p++) s -= Mm[i][p] * Li[p][c];
            Li[i][c] = s / Mm[i][i];
        }
    }
    idx = 0;
    for (int i = 0; i < 8; i++)
        for (int j = 0; j <= i; j++)
            g_Lp[k * 48 + idx++] = 0.70710678118654752f * Li[i][j] * al[j];
}

__global__ void k_init() { g_acc = 0.0; }

// ---------------- per-k offset -> g_Lp[44] ----------------
__global__ void k_off(const float* __restrict__ pi_logits) {
    __shared__ float buf[512];
    int t = threadIdx.x;
    float v = pi_logits[t];
    buf[t] = v;
    __syncthreads();
    for (int s = 256; s > 0; s >>= 1) {
        if (t < s) buf[t] = fmaxf(buf[t], buf[t + s]);
        __syncthreads();
    }
    float mx = buf[0];
    __syncthreads();
    buf[t] = expf(v - mx);
    __syncthreads();
    for (int s = 256; s > 0; s >>= 1) {
        if (t < s) buf[t] += buf[t + s];
        __syncthreads();
    }
    float lse = logf(buf[0]) + mx;
    g_Lp[t * 48 + 44] = -0.5f * ((float)D_N * LOG2PI + g_logdetPsi + g_logdetM[t] + g_mumu[t])
                        + v - lse;
}

// ---------------- fused e1+e2: quad (Cholesky form) + logsumexp + NLL -------
__global__ void __launch_bounds__(256) k_e2() {
    __shared__ float sL[64 * 49];
    int tid = threadIdx.x, warp = tid >> 5, lane = tid & 31;
    int b0 = blockIdx.x * 16 + warp * 2;
    int b1 = b0 + 1;
    const __nv_bfloat16* vr0 = g_V + (size_t)b0 * 4096;
    const __nv_bfloat16* vr1 = g_V + (size_t)b1 * 4096;
    const float* tr0 = g_T + (size_t)b0 * K_N;
    const float* tr1 = g_T + (size_t)b1 * K_N;

    float m0 = -1e30f, s0 = 0.0f, m1 = -1e30f, s1 = 0.0f;
    for (int ch = 0; ch < 8; ch++) {
        int k0 = ch * 64;
        for (int t = tid; t < 64 * 48; t += 256) {
            int kk = t / 48, c = t - kk * 48;
            sL[kk * 49 + c] = g_Lp[(size_t)(k0 + kk) * 48 + c];
        }
        __syncthreads();
#pragma unroll
        for (int half = 0; half < 2; half++) {
            int kl = half * 32 + lane;
            int k  = k0 + kl;
            const float* P = &sL[kl * 49];
#pragma unroll
            for (int bb = 0; bb < 2; bb++) {
                const __nv_bfloat16* vrow = bb ? vr1 : vr0;
                const float*          trow = bb ? tr1 : tr0;
                uint4 raw = *(const uint4*)(vrow + (size_t)k * 8);
                float v[8];
                {
                    float2 f0 = __bfloat1622float2(*(__nv_bfloat162*)&raw.x);
                    float2 f1 = __bfloat1622float2(*(__nv_bfloat162*)&raw.y);
                    float2 f2 = __bfloat1622float2(*(__nv_bfloat162*)&raw.z);
                    float2 f3 = __bfloat1622float2(*(__nv_bfloat162*)&raw.w);
                    v[0] = f0.x; v[1] = f0.y; v[2] = f1.x; v[3] = f1.y;
                    v[4] = f2.x; v[5] = f2.y; v[6] = f3.x; v[7] = f3.y;
                }
#pragma unroll
                for (int j = 0; j < 8; j++) v[j] -= P[36 + j];
                float q = 0.0f;
                int idx = 0;
#pragma unroll
                for (int i = 0; i < 8; i++) {
                    float y = 0.0f;
#pragma unroll
                    for (int j = 0; j <= i; j++) y += P[idx++] * v[j];
                    q += y * y;
                }
                float val = trow[k] + P[44] + q;
                if (bb == 0) {
                    if (val > m0) { s0 = s0 * __expf(m0 - val) + 1.0f; m0 = val; }
                    else          { s0 += __expf(val - m0); }
                } else {
                    if (val > m1) { s1 = s1 * __expf(m1 - val) + 1.0f; m1 = val; }
                    else          { s1 += __expf(val - m1); }
                }
            }
        }
        __syncthreads();
    }
#pragma unroll
    for (int o = 16; o; o >>= 1) {
        float mo = __shfl_xor_sync(0xffffffffu, m0, o);
        float so = __shfl_xor_sync(0xffffffffu, s0, o);
        float M = fmaxf(m0, mo);
        s0 = s0 * __expf(m0 - M) + so * __expf(mo - M);
        m0 = M;
        mo = __shfl_xor_sync(0xffffffffu, m1, o);
        so = __shfl_xor_sync(0xffffffffu, s1, o);
        M = fmaxf(m1, mo);
        s1 = s1 * __expf(m1 - M) + so * __expf(mo - M);
        m1 = M;
    }
    if (lane == 0) {
        float lp = (__logf(s0) + m0 - 0.5f * g_r[b0]) + (__logf(s1) + m1 - 0.5f * g_r[b1]);
        atomicAdd(&g_acc, (double)(-lp));
    }
}

__global__ void k_fin(float* out) { out[0] = (float)(g_acc * (1.0 / (double)B_N)); }

// ---------------- launch: multi-stream fork/join for overlap ----------------
extern "C" void kernel_launch(void* const* d_in, const int* in_sizes, int n_in,
                              void* d_out, int out_size) {
    const float* x         = (const float*)d_in[0];
    const float* mu        = (const float*)d_in[1];
    const float* dir_raw   = (const float*)d_in[2];
    const float* scale_rho = (const float*)d_in[3];
    const float* psi_rho   = (const float*)d_in[4];
    const float* pi_logits = (const float*)d_in[5];
    float* out = (float*)d_out;

    static cudaStream_t s_aux = nullptr;
    static cudaEvent_t ev_fork1, ev_join1, ev_fork2, ev_join2;
    if (!s_aux) {
        cudaStreamCreateWithFlags(&s_aux, cudaStreamNonBlocking);
        cudaEventCreateWithFlags(&ev_fork1, cudaEventDisableTiming);
        cudaEventCreateWithFlags(&ev_join1, cudaEventDisableTiming);
        cudaEventCreateWithFlags(&ev_fork2, cudaEventDisableTiming);
        cudaEventCreateWithFlags(&ev_join2, cudaEventDisableTiming);
        cudaFuncSetAttribute(k_mma_gemm, cudaFuncAttributeMaxDynamicSharedMemorySize, GEMM_SMEM);
    }

    // main: psi, then fork
    k_psi<<<1, 1024>>>(psi_rho);
    cudaEventRecord(ev_fork1, 0);
    cudaStreamWaitEvent(s_aux, ev_fork1, 0);

    // aux: X conversion (|| with pB on main)
    k_cvt<<<B_N / 8, 256, 0, s_aux>>>(x);
    cudaEventRecord(ev_join1, s_aux);

    // main: W construction
    pB<<<dim3(4, K_N), 256>>>(dir_raw, mu);

    // fork 2: pC/init/off chain on aux (|| with GEMM on main)
    cudaEventRecord(ev_fork2, 0);
    cudaStreamWaitEvent(s_aux, ev_fork2, 0);   // aux now ordered after k_cvt AND pB
    pC<<<4, 128, 0, s_aux>>>(scale_rho);
    k_init<<<1, 1, 0, s_aux>>>();
    k_off<<<1, 512, 0, s_aux>>>(pi_logits);
    cudaEventRecord(ev_join2, s_aux);

    // main: GEMM (needs g_XB from aux + g_WB from pB)
    cudaStreamWaitEvent(0, ev_join1, 0);
    dim3 gg(36, 64);
    k_mma_gemm<<<gg, 128, GEMM_SMEM>>>();

    // main: epilogue (needs GEMM + aux chain)
    cudaStreamWaitEvent(0, ev_join2, 0);
    k_e2<<<B_N / 16, 256>>>();
    k_fin<<<1, 1>>>(out);
}

// round 16
// speedup vs baseline: 1.1378x; 1.0001x over previous
#include <cuda_runtime.h>
#include <cuda_bf16.h>
#include <math.h>
#include <stdint.h>

#define B_N    8192
#define K_N    512
#define D_N    2048
#define Q_N    8
#define LOG2PI 1.8378770664093453f
#define EPSC   1e-5f

// ---------------- scratch (static __device__, no allocation) ----------------
__device__ __nv_bfloat16 g_XB[(size_t)B_N * D_N];   // X in bf16
__device__ __nv_bfloat16 g_WB[(size_t)4608 * D_N];  // [512 pm | 4096 pi*dv] x D, bf16
__device__ float         g_T [(size_t)B_N * K_N];   // t1[b][k]
__device__ __nv_bfloat16 g_V [(size_t)B_N * 4096];  // vtilde GEMM out, bf16
__device__ float  g_psi_inv[D_N];
__device__ float  g_logdetPsi;
__device__ float  g_r[B_N];
__device__ float  g_Sacc[K_N * 4 * 56];             // per-chunk: 36 S + 8 wm + 8 ns + 1 mm
__device__ float  g_Lp[K_N * 48];                   // [0..35] sqrt(.5)*Linv*al_col | 8 wm | off
__device__ float  g_logdetM[K_N];
__device__ float  g_mumu[K_N];
__device__ double g_acc;

__device__ __forceinline__ float softplusf(float x) {
    return x > 20.0f ? x : log1pf(expf(x));
}
__device__ __forceinline__ uint32_t smem_u32(const void* p) {
    uint32_t a;
    asm("{ .reg .u64 t; cvta.to.shared.u64 t, %1; cvt.u32.u64 %0, t; }" : "=r"(a) : "l"(p));
    return a;
}
__device__ __forceinline__ void cp_async16(uint32_t saddr, const void* gaddr) {
    asm volatile("cp.async.cg.shared.global [%0], [%1], 16;" :: "r"(saddr), "l"(gaddr));
}
__device__ __forceinline__ float warp_sum(float v) {
#pragma unroll
    for (int o = 16; o; o >>= 1) v += __shfl_xor_sync(0xffffffffu, v, o);
    return v;
}

// ---------------- psi precompute ----------------
__global__ void k_psi(const float* __restrict__ psi_rho) {
    __shared__ float ssum;
    int tid = threadIdx.x;
    if (tid == 0) ssum = 0.0f;
    __syncthreads();
    float l = 0.0f;
    for (int d = tid; d < D_N; d += 1024) {
        float p = softplusf(psi_rho[d]) + EPSC;
        g_psi_inv[d] = 1.0f / p;
        l += logf(p);
    }
    l = warp_sum(l);
    if ((tid & 31) == 0) atomicAdd(&ssum, l);
    __syncthreads();
    if (tid == 0) g_logdetPsi = ssum;
}

// ---------------- X -> bf16 + r[b] (warp per row) ----------------
__global__ void k_cvt(const float* __restrict__ x) {
    int warp = threadIdx.x >> 5, lane = threadIdx.x & 31;
    int b = blockIdx.x * 8 + warp;
    const float* xb = x + (size_t)b * D_N;
    __nv_bfloat16* ob = g_XB + (size_t)b * D_N;
    float r = 0.0f;
    for (int d = lane * 4; d < D_N; d += 128) {
        float4 xv = *(const float4*)(xb + d);
        float4 pv = *(const float4*)(g_psi_inv + d);
        r += xv.x * xv.x * pv.x + xv.y * xv.y * pv.y
           + xv.z * xv.z * pv.z + xv.w * xv.w * pv.w;
        __nv_bfloat162 h0 = __float22bfloat162_rn(make_float2(xv.x, xv.y));
        __nv_bfloat162 h1 = __float22bfloat162_rn(make_float2(xv.z, xv.w));
        uint2 hb;
        hb.x = *(uint32_t*)&h0; hb.y = *(uint32_t*)&h1;
        *(uint2*)(ob + d) = hb;
    }
    r = warp_sum(r);
    if (lane == 0) g_r[b] = r;
}

// ---------------- pB: per-k stats (S, wm, ns, mm) + Wcat writes -------------
__global__ void pB(const float* __restrict__ dir_raw,
                   const float* __restrict__ mu) {
    int k = blockIdx.y, chunk = blockIdx.x, tid = threadIdx.x, lane = tid & 31;
    __shared__ float s_acc[53];
    if (tid < 53) s_acc[tid] = 0.0f;
    __syncthreads();

    const float* dirk = dir_raw + (size_t)k * D_N * Q_N;
    const float* muk  = mu + (size_t)k * D_N;

    float S[36], wm[8], ns[8], mm = 0.0f;
#pragma unroll
    for (int i = 0; i < 36; i++) S[i] = 0.0f;
#pragma unroll
    for (int i = 0; i < 8; i++) { wm[i] = 0.0f; ns[i] = 0.0f; }

    int d0 = chunk * 512;
#pragma unroll
    for (int it = 0; it < 2; it++) {
        int d = d0 + tid + it * 256;
        float dv[8];
        float4 a  = *(const float4*)(dirk + (size_t)d * 8);
        float4 b4 = *(const float4*)(dirk + (size_t)d * 8 + 4);
        dv[0] = a.x; dv[1] = a.y; dv[2] = a.z; dv[3] = a.w;
        dv[4] = b4.x; dv[5] = b4.y; dv[6] = b4.z; dv[7] = b4.w;
        float pi = g_psi_inv[d];
        float m  = muk[d];
        float pim = pi * m;
        mm += m * pim;
        int idx = 0;
#pragma unroll
        for (int i = 0; i < 8; i++) {
            float pdi = pi * dv[i];
            wm[i] += m * pdi;
            ns[i] += dv[i] * dv[i];
#pragma unroll
            for (int j = 0; j <= i; j++) S[idx++] += pdi * dv[j];
        }
        g_WB[(size_t)k * D_N + d] = __float2bfloat16(pim);
#pragma unroll
        for (int j = 0; j < 8; j++)
            g_WB[(size_t)(K_N + k * 8 + j) * D_N + d] = __float2bfloat16(pi * dv[j]);
    }
#pragma unroll
    for (int i = 0; i < 36; i++) {
        S[i] = warp_sum(S[i]);
        if (lane == 0) atomicAdd(&s_acc[i], S[i]);
    }
#pragma unroll
    for (int j = 0; j < 8; j++) {
        wm[j] = warp_sum(wm[j]);
        if (lane == 0) atomicAdd(&s_acc[36 + j], wm[j]);
        ns[j] = warp_sum(ns[j]);
        if (lane == 0) atomicAdd(&s_acc[44 + j], ns[j]);
    }
    mm = warp_sum(mm);
    if (lane == 0) atomicAdd(&s_acc[52], mm);
    __syncthreads();
    if (tid < 53) g_Sacc[(size_t)(k * 4 + chunk) * 56 + tid] = s_acc[tid];
}

// ---------------- bf16 MMA GEMM: 128 threads, 4 warps of 64x64 --------------
#define BK       32
#define KBLOCKS  (D_N / BK)      // 64
#define STAGES   4
#define TILE_A   8192
#define TILE_B   8192
#define TILE_AB  (TILE_A + TILE_B)
#define GEMM_SMEM (STAGES * TILE_AB)   // 64 KB

__global__ void __launch_bounds__(128, 3) k_mma_gemm() {
    extern __shared__ __align__(128) char smem[];
    const int tid  = threadIdx.x;
    const int wid  = tid >> 5;
    const int lane = tid & 31;
    const int warp_m = wid & 1;    // 2 x 64 rows
    const int warp_n = wid >> 1;   // 2 x 64 cols
    const int bx = blockIdx.x;     // 0..35 (bx<4 -> t1 region, else v region)
    const int by = blockIdx.y;     // 0..63

    const uint32_t sbase = smem_u32(smem);
    const __nv_bfloat16* Ag = g_XB + (size_t)(by * 128) * D_N;
    const __nv_bfloat16* Bg = g_WB + (size_t)(bx * 128) * D_N;

    auto load_stage = [&](int s, int kb) {
        uint32_t aB = sbase + s * TILE_AB;
        uint32_t bB = aB + TILE_A;
#pragma unroll
        for (int i = 0; i < 4; i++) {
            int id  = tid + i * 128;     // 0..511
            int row = id >> 2;
            int ch  = id & 3;
            int sw  = ch ^ ((row >> 1) & 3);
            cp_async16(aB + row * 64 + sw * 16, Ag + (size_t)row * D_N + kb * BK + ch * 8);
            cp_async16(bB + row * 64 + sw * 16, Bg + (size_t)row * D_N + kb * BK + ch * 8);
        }
        asm volatile("cp.async.commit_group;");
    };

    float acc[4][8][4];
#pragma unroll
    for (int mi = 0; mi < 4; mi++)
#pragma unroll
        for (int ni = 0; ni < 8; ni++)
#pragma unroll
            for (int j = 0; j < 4; j++) acc[mi][ni][j] = 0.0f;

    load_stage(0, 0);
    load_stage(1, 1);
    load_stage(2, 2);

    for (int kb = 0; kb < KBLOCKS; kb++) {
        if (kb + 2 < KBLOCKS)       asm volatile("cp.async.wait_group 2;");
        else if (kb + 2 == KBLOCKS) asm volatile("cp.async.wait_group 1;");
        else                        asm volatile("cp.async.wait_group 0;");
        __syncthreads();
        if (kb + 3 < KBLOCKS) load_stage((kb + 3) & 3, kb + 3);
        uint32_t aB = sbase + (kb & 3) * TILE_AB;
        uint32_t bB = aB + TILE_A;
#pragma unroll
        for (int ks = 0; ks < 2; ks++) {
            uint32_t a[4][4];
#pragma unroll
            for (int mi = 0; mi < 4; mi++) {
                int r  = warp_m * 64 + mi * 16 + (lane & 15);
                int ch = ks * 2 + (lane >> 4);
                uint32_t ad = aB + r * 64 + ((ch ^ ((r >> 1) & 3)) << 4);
                asm volatile("ldmatrix.sync.aligned.m8n8.x4.shared.b16 {%0,%1,%2,%3}, [%4];"
                             : "=r"(a[mi][0]), "=r"(a[mi][1]), "=r"(a[mi][2]), "=r"(a[mi][3])
                             : "r"(ad));
            }
#pragma unroll
            for (int p = 0; p < 4; p++) {
                uint32_t b0[2], b1[2];
                int g  = lane >> 3, rl = lane & 7;
                int r  = warp_n * 64 + p * 16 + (g >> 1) * 8 + rl;
                int ch = ks * 2 + (g & 1);
                uint32_t bd = bB + r * 64 + ((ch ^ ((r >> 1) & 3)) << 4);
                asm volatile("ldmatrix.sync.aligned.m8n8.x4.shared.b16 {%0,%1,%2,%3}, [%4];"
                             : "=r"(b0[0]), "=r"(b0[1]), "=r"(b1[0]), "=r"(b1[1])
                             : "r"(bd));
#pragma unroll
                for (int mi = 0; mi < 4; mi++) {
                    asm volatile(
                        "mma.sync.aligned.m16n8k16.row.col.f32.bf16.bf16.f32 "
                        "{%0,%1,%2,%3}, {%4,%5,%6,%7}, {%8,%9}, {%0,%1,%2,%3};"
                        : "+f"(acc[mi][2*p][0]), "+f"(acc[mi][2*p][1]),
                          "+f"(acc[mi][2*p][2]), "+f"(acc[mi][2*p][3])
                        : "r"(a[mi][0]), "r"(a[mi][1]), "r"(a[mi][2]), "r"(a[mi][3]),
                          "r"(b0[0]), "r"(b0[1]));
                    asm volatile(
                        "mma.sync.aligned.m16n8k16.row.col.f32.bf16.bf16.f32 "
                        "{%0,%1,%2,%3}, {%4,%5,%6,%7}, {%8,%9}, {%0,%1,%2,%3};"
                        : "+f"(acc[mi][2*p+1][0]), "+f"(acc[mi][2*p+1][1]),
                          "+f"(acc[mi][2*p+1][2]), "+f"(acc[mi][2*p+1][3])
                        : "r"(a[mi][0]), "r"(a[mi][1]), "r"(a[mi][2]), "r"(a[mi][3]),
                          "r"(b1[0]), "r"(b1[1]));
                }
            }
        }
    }

    const int gq = lane >> 2;
    const int tg = lane & 3;

    if (bx < 4) {
#pragma unroll
        for (int mi = 0; mi < 4; mi++) {
            int r0 = by * 128 + warp_m * 64 + mi * 16 + gq;
            int r1 = r0 + 8;
#pragma unroll
            for (int ni = 0; ni < 8; ni++) {
                int col = bx * 128 + warp_n * 64 + ni * 8 + tg * 2;
                *(float2*)&g_T[(size_t)r0 * K_N + col] = make_float2(acc[mi][ni][0], acc[mi][ni][1]);
                *(float2*)&g_T[(size_t)r1 * K_N + col] = make_float2(acc[mi][ni][2], acc[mi][ni][3]);
            }
        }
    } else {
#pragma unroll
        for (int mi = 0; mi < 4; mi++) {
            int r0 = by * 128 + warp_m * 64 + mi * 16 + gq;
            int r1 = r0 + 8;
#pragma unroll
            for (int ni = 0; ni < 8; ni++) {
                int col = (bx - 4) * 128 + warp_n * 64 + ni * 8 + tg * 2;
                __nv_bfloat162 lo = __float22bfloat162_rn(make_float2(acc[mi][ni][0], acc[mi][ni][1]));
                __nv_bfloat162 hi = __float22bfloat162_rn(make_float2(acc[mi][ni][2], acc[mi][ni][3]));
                *(__nv_bfloat162*)&g_V[(size_t)r0 * 4096 + col] = lo;
                *(__nv_bfloat162*)&g_V[(size_t)r1 * 4096 + col] = hi;
            }
        }
    }
}

// ---------------- pC: reduce chunks, alpha, Cholesky -> packed Lp -----------
__global__ void pC(const float* __restrict__ scale_rho) {
    int k = blockIdx.x * 128 + threadIdx.x;
    if (k >= K_N) return;
    float buf[53];
    for (int i = 0; i < 53; i++) {
        float s = 0.0f;
        for (int c = 0; c < 4; c++) s += g_Sacc[(size_t)(k * 4 + c) * 56 + i];
        buf[i] = s;
    }
    float al[8];
#pragma unroll
    for (int j = 0; j < 8; j++) {
        float sp = softplusf(scale_rho[k * 8 + j]);
        al[j] = sp / fmaxf(sqrtf(buf[44 + j]), EPSC);
    }

    float Mm[8][8];
    int idx = 0;
    for (int i = 0; i < 8; i++)
        for (int j = 0; j <= i; j++)
            Mm[i][j] = al[i] * al[j] * buf[idx++] + (i == j ? 1.0f : 0.0f);
    for (int i = 0; i < 8; i++) {
        for (int j = 0; j <= i; j++) {
            float s = Mm[i][j];
            for (int p = 0; p < j; p++) s -= Mm[i][p] * Mm[j][p];
            if (i == j) Mm[i][i] = sqrtf(s);
            else        Mm[i][j] = s / Mm[j][j];
        }
    }
    float ld = 0.0f;
    for (int i = 0; i < 8; i++) ld += logf(Mm[i][i]);
    g_logdetM[k] = 2.0f * ld;
    g_mumu[k]    = buf[52];
    for (int j = 0; j < 8; j++) g_Lp[k * 48 + 36 + j] = buf[36 + j];

    float Li[8][8];
    for (int i = 0; i < 8; i++)
        for (int j = 0; j < 8; j++) Li[i][j] = 0.0f;
    for (int c = 0; c < 8; c++) {
        for (int i = c; i < 8; i++) {
            float s = (i == c) ? 1.0f : 0.0f;
            for (int p = c; p < i; p++) s -= Mm[i][p] * Li[p][c];
            Li[i][c] = s / Mm[i][i];
        }
    }
    idx = 0;
    for (int i = 0; i < 8; i++)
        for (int j = 0; j <= i; j++)
            g_Lp[k * 48 + idx++] = 0.70710678118654752f * Li[i][j] * al[j];
}

__global__ void k_init() { g_acc = 0.0; }

// ---------------- per-k offset -> g_Lp[44] ----------------
__global__ void k_off(const float* __restrict__ pi_logits) {
    __shared__ float buf[512];
    int t = threadIdx.x;
    float v = pi_logits[t];
    buf[t] = v;
    __syncthreads();
    for (int s = 256; s > 0; s >>= 1) {
        if (t < s) buf[t] = fmaxf(buf[t], buf[t + s]);
        __syncthreads();
    }
    float mx = buf[0];
    __syncthreads();
    buf[t] = expf(v - mx);
    __syncthreads();
    for (int s = 256; s > 0; s >>= 1) {
        if (t < s) buf[t] += buf[t + s];
        __syncthreads();
    }
    float lse = logf(buf[0]) + mx;
    g_Lp[t * 48 + 44] = -0.5f * ((float)D_N * LOG2PI + g_logdetPsi + g_logdetM[t] + g_mumu[t])
                        + v - lse;
}

// ---------------- fused e1+e2: quad (Cholesky form) + logsumexp + NLL -------
__global__ void __launch_bounds__(256) k_e2() {
    __shared__ float sL[64 * 49];
    int tid = threadIdx.x, warp = tid >> 5, lane = tid & 31;
    int b0 = blockIdx.x * 16 + warp * 2;
    int b1 = b0 + 1;
    const __nv_bfloat16* vr0 = g_V + (size_t)b0 * 4096;
    const __nv_bfloat16* vr1 = g_V + (size_t)b1 * 4096;
    const float* tr0 = g_T + (size_t)b0 * K_N;
    const float* tr1 = g_T + (size_t)b1 * K_N;

    float m0 = -1e30f, s0 = 0.0f, m1 = -1e30f, s1 = 0.0f;
    for (int ch = 0; ch < 8; ch++) {
        int k0 = ch * 64;
        for (int t = tid; t < 64 * 48; t += 256) {
            int kk = t / 48, c = t - kk * 48;
            sL[kk * 49 + c] = g_Lp[(size_t)(k0 + kk) * 48 + c];
        }
        __syncthreads();
#pragma unroll
        for (int half = 0; half < 2; half++) {
            int kl = half * 32 + lane;
            int k  = k0 + kl;
            const float* P = &sL[kl * 49];
#pragma unroll
            for (int bb = 0; bb < 2; bb++) {
                const __nv_bfloat16* vrow = bb ? vr1 : vr0;
                const float*          trow = bb ? tr1 : tr0;
                uint4 raw = *(const uint4*)(vrow + (size_t)k * 8);
                float v[8];
                {
                    float2 f0 = __bfloat1622float2(*(__nv_bfloat162*)&raw.x);
                    float2 f1 = __bfloat1622float2(*(__nv_bfloat162*)&raw.y);
                    float2 f2 = __bfloat1622float2(*(__nv_bfloat162*)&raw.z);
                    float2 f3 = __bfloat1622float2(*(__nv_bfloat162*)&raw.w);
                    v[0] = f0.x; v[1] = f0.y; v[2] = f1.x; v[3] = f1.y;
                    v[4] = f2.x; v[5] = f2.y; v[6] = f3.x; v[7] = f3.y;
                }
#pragma unroll
                for (int j = 0; j < 8; j++) v[j] -= P[36 + j];
                float q = 0.0f;
                int idx = 0;
#pragma unroll
                for (int i = 0; i < 8; i++) {
                    float y = 0.0f;
#pragma unroll
                    for (int j = 0; j <= i; j++) y += P[idx++] * v[j];
                    q += y * y;
                }
                float val = trow[k] + P[44] + q;
                if (bb == 0) {
                    if (val > m0) { s0 = s0 * __expf(m0 - val) + 1.0f; m0 = val; }
                    else          { s0 += __expf(val - m0); }
                } else {
                    if (val > m1) { s1 = s1 * __expf(m1 - val) + 1.0f; m1 = val; }
                    else          { s1 += __expf(val - m1); }
                }
            }
        }
        __syncthreads();
    }
#pragma unroll
    for (int o = 16; o; o >>= 1) {
        float mo = __shfl_xor_sync(0xffffffffu, m0, o);
        float so = __shfl_xor_sync(0xffffffffu, s0, o);
        float M = fmaxf(m0, mo);
        s0 = s0 * __expf(m0 - M) + so * __expf(mo - M);
        m0 = M;
        mo = __shfl_xor_sync(0xffffffffu, m1, o);
        so = __shfl_xor_sync(0xffffffffu, s1, o);
        M = fmaxf(m1, mo);
        s1 = s1 * __expf(m1 - M) + so * __expf(mo - M);
        m1 = M;
    }
    if (lane == 0) {
        float lp = (__logf(s0) + m0 - 0.5f * g_r[b0]) + (__logf(s1) + m1 - 0.5f * g_r[b1]);
        atomicAdd(&g_acc, (double)(-lp));
    }
}

__global__ void k_fin(float* out) { out[0] = (float)(g_acc * (1.0 / (double)B_N)); }

// ---------------- launch: multi-stream fork/join for overlap ----------------
extern "C" void kernel_launch(void* const* d_in, const int* in_sizes, int n_in,
                              void* d_out, int out_size) {
    const float* x         = (const float*)d_in[0];
    const float* mu        = (const float*)d_in[1];
    const float* dir_raw   = (const float*)d_in[2];
    const float* scale_rho = (const float*)d_in[3];
    const float* psi_rho   = (const float*)d_in[4];
    const float* pi_logits = (const float*)d_in[5];
    float* out = (float*)d_out;

    static cudaStream_t s_aux = nullptr;
    static cudaEvent_t ev_fork1, ev_join1, ev_fork2, ev_join2;
    if (!s_aux) {
        cudaStreamCreateWithFlags(&s_aux, cudaStreamNonBlocking);
        cudaEventCreateWithFlags(&ev_fork1, cudaEventDisableTiming);
        cudaEventCreateWithFlags(&ev_join1, cudaEventDisableTiming);
        cudaEventCreateWithFlags(&ev_fork2, cudaEventDisableTiming);
        cudaEventCreateWithFlags(&ev_join2, cudaEventDisableTiming);
        cudaFuncSetAttribute(k_mma_gemm, cudaFuncAttributeMaxDynamicSharedMemorySize, GEMM_SMEM);
    }

    // main: psi, then fork
    k_psi<<<1, 1024>>>(psi_rho);
    cudaEventRecord(ev_fork1, 0);
    cudaStreamWaitEvent(s_aux, ev_fork1, 0);

    // aux: X conversion (|| with pB on main)
    k_cvt<<<B_N / 8, 256, 0, s_aux>>>(x);
    cudaEventRecord(ev_join1, s_aux);

    // main: W construction
    pB<<<dim3(4, K_N), 256>>>(dir_raw, mu);

    // fork 2: pC/init/off chain on aux (|| with GEMM on main)
    cudaEventRecord(ev_fork2, 0);
    cudaStreamWaitEvent(s_aux, ev_fork2, 0);   // aux now ordered after k_cvt AND pB
    pC<<<4, 128, 0, s_aux>>>(scale_rho);
    k_init<<<1, 1, 0, s_aux>>>();
    k_off<<<1, 512, 0, s_aux>>>(pi_logits);
    cudaEventRecord(ev_join2, s_aux);

    // main: GEMM (needs g_XB from aux + g_WB from pB)
    cudaStreamWaitEvent(0, ev_join1, 0);
    dim3 gg(36, 64);
    k_mma_gemm<<<gg, 128, GEMM_SMEM>>>();

    // main: epilogue (needs GEMM + aux chain)
    cudaStreamWaitEvent(0, ev_join2, 0);
    k_e2<<<B_N / 16, 256>>>();
    k_fin<<<1, 1>>>(out);
}

// round 17
// speedup vs baseline: 1.1724x; 1.0304x over previous
#include <cuda_runtime.h>
#include <cuda_bf16.h>
#include <math.h>
#include <stdint.h>

#define B_N    8192
#define K_N    512
#define D_N    2048
#define Q_N    8
#define LOG2PI 1.8378770664093453f
#define EPSC   1e-5f

// ---------------- scratch (static __device__, no allocation) ----------------
__device__ __nv_bfloat16 g_XB[(size_t)B_N * D_N];   // X in bf16
__device__ __nv_bfloat16 g_WB[(size_t)4608 * D_N];  // [512 pm | 4096 pi*dv] x D, bf16
__device__ float         g_T [(size_t)B_N * K_N];   // t1[b][k]
__device__ __nv_bfloat16 g_V [(size_t)B_N * 4096];  // vtilde GEMM out, bf16
__device__ float  g_psi_inv[D_N];
__device__ float  g_logdetPsi;
__device__ float  g_r[B_N];
__device__ float  g_Sacc[K_N * 4 * 56];             // per-chunk: 36 S + 8 wm + 8 ns + 1 mm
__device__ float  g_Lp[K_N * 48];                   // [0..35] sqrt(.5)*Linv*al_col | 8 wm | off
__device__ float  g_logdetM[K_N];
__device__ float  g_mumu[K_N];
__device__ double g_acc;
__device__ int    g_cnt;

__device__ __forceinline__ float softplusf(float x) {
    return x > 20.0f ? x : log1pf(expf(x));
}
__device__ __forceinline__ uint32_t smem_u32(const void* p) {
    uint32_t a;
    asm("{ .reg .u64 t; cvta.to.shared.u64 t, %1; cvt.u32.u64 %0, t; }" : "=r"(a) : "l"(p));
    return a;
}
__device__ __forceinline__ void cp_async16(uint32_t saddr, const void* gaddr) {
    asm volatile("cp.async.cg.shared.global [%0], [%1], 16;" :: "r"(saddr), "l"(gaddr));
}
__device__ __forceinline__ float warp_sum(float v) {
#pragma unroll
    for (int o = 16; o; o >>= 1) v += __shfl_xor_sync(0xffffffffu, v, o);
    return v;
}

// ---------------- psi precompute ----------------
__global__ void k_psi(const float* __restrict__ psi_rho) {
    __shared__ float ssum;
    int tid = threadIdx.x;
    if (tid == 0) ssum = 0.0f;
    __syncthreads();
    float l = 0.0f;
    for (int d = tid; d < D_N; d += 1024) {
        float p = softplusf(psi_rho[d]) + EPSC;
        g_psi_inv[d] = 1.0f / p;
        l += logf(p);
    }
    l = warp_sum(l);
    if ((tid & 31) == 0) atomicAdd(&ssum, l);
    __syncthreads();
    if (tid == 0) g_logdetPsi = ssum;
}

// ---------------- X -> bf16 + r[b] (warp per row) ----------------
__global__ void k_cvt(const float* __restrict__ x) {
    int warp = threadIdx.x >> 5, lane = threadIdx.x & 31;
    int b = blockIdx.x * 8 + warp;
    const float* xb = x + (size_t)b * D_N;
    __nv_bfloat16* ob = g_XB + (size_t)b * D_N;
    float r = 0.0f;
    for (int d = lane * 4; d < D_N; d += 128) {
        float4 xv = *(const float4*)(xb + d);
        float4 pv = *(const float4*)(g_psi_inv + d);
        r += xv.x * xv.x * pv.x + xv.y * xv.y * pv.y
           + xv.z * xv.z * pv.z + xv.w * xv.w * pv.w;
        __nv_bfloat162 h0 = __float22bfloat162_rn(make_float2(xv.x, xv.y));
        __nv_bfloat162 h1 = __float22bfloat162_rn(make_float2(xv.z, xv.w));
        uint2 hb;
        hb.x = *(uint32_t*)&h0; hb.y = *(uint32_t*)&h1;
        *(uint2*)(ob + d) = hb;
    }
    r = warp_sum(r);
    if (lane == 0) g_r[b] = r;
}

// ---------------- pB: per-k stats (S, wm, ns, mm) + Wcat writes -------------
__global__ void pB(const float* __restrict__ dir_raw,
                   const float* __restrict__ mu) {
    int k = blockIdx.y, chunk = blockIdx.x, tid = threadIdx.x, lane = tid & 31;
    __shared__ float s_acc[53];
    if (tid < 53) s_acc[tid] = 0.0f;
    __syncthreads();

    const float* dirk = dir_raw + (size_t)k * D_N * Q_N;
    const float* muk  = mu + (size_t)k * D_N;

    float S[36], wm[8], ns[8], mm = 0.0f;
#pragma unroll
    for (int i = 0; i < 36; i++) S[i] = 0.0f;
#pragma unroll
    for (int i = 0; i < 8; i++) { wm[i] = 0.0f; ns[i] = 0.0f; }

    int d0 = chunk * 512;
#pragma unroll
    for (int it = 0; it < 2; it++) {
        int d = d0 + tid + it * 256;
        float dv[8];
        float4 a  = *(const float4*)(dirk + (size_t)d * 8);
        float4 b4 = *(const float4*)(dirk + (size_t)d * 8 + 4);
        dv[0] = a.x; dv[1] = a.y; dv[2] = a.z; dv[3] = a.w;
        dv[4] = b4.x; dv[5] = b4.y; dv[6] = b4.z; dv[7] = b4.w;
        float pi = g_psi_inv[d];
        float m  = muk[d];
        float pim = pi * m;
        mm += m * pim;
        int idx = 0;
#pragma unroll
        for (int i = 0; i < 8; i++) {
            float pdi = pi * dv[i];
            wm[i] += m * pdi;
            ns[i] += dv[i] * dv[i];
#pragma unroll
            for (int j = 0; j <= i; j++) S[idx++] += pdi * dv[j];
        }
        g_WB[(size_t)k * D_N + d] = __float2bfloat16(pim);
#pragma unroll
        for (int j = 0; j < 8; j++)
            g_WB[(size_t)(K_N + k * 8 + j) * D_N + d] = __float2bfloat16(pi * dv[j]);
    }
#pragma unroll
    for (int i = 0; i < 36; i++) {
        S[i] = warp_sum(S[i]);
        if (lane == 0) atomicAdd(&s_acc[i], S[i]);
    }
#pragma unroll
    for (int j = 0; j < 8; j++) {
        wm[j] = warp_sum(wm[j]);
        if (lane == 0) atomicAdd(&s_acc[36 + j], wm[j]);
        ns[j] = warp_sum(ns[j]);
        if (lane == 0) atomicAdd(&s_acc[44 + j], ns[j]);
    }
    mm = warp_sum(mm);
    if (lane == 0) atomicAdd(&s_acc[52], mm);
    __syncthreads();
    if (tid < 53) g_Sacc[(size_t)(k * 4 + chunk) * 56 + tid] = s_acc[tid];
}

// ---------------- bf16 MMA GEMM: 128 threads, 4 warps of 64x64 --------------
#define BK       32
#define KBLOCKS  (D_N / BK)      // 64
#define STAGES   4
#define TILE_A   8192
#define TILE_B   8192
#define TILE_AB  (TILE_A + TILE_B)
#define GEMM_SMEM (STAGES * TILE_AB)   // 64 KB

__global__ void __launch_bounds__(128, 3) k_mma_gemm(int by_base) {
    extern __shared__ __align__(128) char smem[];
    const int tid  = threadIdx.x;
    const int wid  = tid >> 5;
    const int lane = tid & 31;
    const int warp_m = wid & 1;    // 2 x 64 rows
    const int warp_n = wid >> 1;   // 2 x 64 cols
    const int bx = blockIdx.x;     // 0..35 (bx<4 -> t1 region, else v region)
    const int by = by_base + blockIdx.y;

    const uint32_t sbase = smem_u32(smem);
    const __nv_bfloat16* Ag = g_XB + (size_t)(by * 128) * D_N;
    const __nv_bfloat16* Bg = g_WB + (size_t)(bx * 128) * D_N;

    auto load_stage = [&](int s, int kb) {
        uint32_t aB = sbase + s * TILE_AB;
        uint32_t bB = aB + TILE_A;
#pragma unroll
        for (int i = 0; i < 4; i++) {
            int id  = tid + i * 128;     // 0..511
            int row = id >> 2;
            int ch  = id & 3;
            int sw  = ch ^ ((row >> 1) & 3);
            cp_async16(aB + row * 64 + sw * 16, Ag + (size_t)row * D_N + kb * BK + ch * 8);
            cp_async16(bB + row * 64 + sw * 16, Bg + (size_t)row * D_N + kb * BK + ch * 8);
        }
        asm volatile("cp.async.commit_group;");
    };

    float acc[4][8][4];
#pragma unroll
    for (int mi = 0; mi < 4; mi++)
#pragma unroll
        for (int ni = 0; ni < 8; ni++)
#pragma unroll
            for (int j = 0; j < 4; j++) acc[mi][ni][j] = 0.0f;

    load_stage(0, 0);
    load_stage(1, 1);
    load_stage(2, 2);

    for (int kb = 0; kb < KBLOCKS; kb++) {
        if (kb + 2 < KBLOCKS)       asm volatile("cp.async.wait_group 2;");
        else if (kb + 2 == KBLOCKS) asm volatile("cp.async.wait_group 1;");
        else                        asm volatile("cp.async.wait_group 0;");
        __syncthreads();
        if (kb + 3 < KBLOCKS) load_stage((kb + 3) & 3, kb + 3);
        uint32_t aB = sbase + (kb & 3) * TILE_AB;
        uint32_t bB = aB + TILE_A;
#pragma unroll
        for (int ks = 0; ks < 2; ks++) {
            uint32_t a[4][4];
#pragma unroll
            for (int mi = 0; mi < 4; mi++) {
                int r  = warp_m * 64 + mi * 16 + (lane & 15);
                int ch = ks * 2 + (lane >> 4);
                uint32_t ad = aB + r * 64 + ((ch ^ ((r >> 1) & 3)) << 4);
                asm volatile("ldmatrix.sync.aligned.m8n8.x4.shared.b16 {%0,%1,%2,%3}, [%4];"
                             : "=r"(a[mi][0]), "=r"(a[mi][1]), "=r"(a[mi][2]), "=r"(a[mi][3])
                             : "r"(ad));
            }
#pragma unroll
            for (int p = 0; p < 4; p++) {
                uint32_t b0[2], b1[2];
                int g  = lane >> 3, rl = lane & 7;
                int r  = warp_n * 64 + p * 16 + (g >> 1) * 8 + rl;
                int ch = ks * 2 + (g & 1);
                uint32_t bd = bB + r * 64 + ((ch ^ ((r >> 1) & 3)) << 4);
                asm volatile("ldmatrix.sync.aligned.m8n8.x4.shared.b16 {%0,%1,%2,%3}, [%4];"
                             : "=r"(b0[0]), "=r"(b0[1]), "=r"(b1[0]), "=r"(b1[1])
                             : "r"(bd));
#pragma unroll
                for (int mi = 0; mi < 4; mi++) {
                    asm volatile(
                        "mma.sync.aligned.m16n8k16.row.col.f32.bf16.bf16.f32 "
                        "{%0,%1,%2,%3}, {%4,%5,%6,%7}, {%8,%9}, {%0,%1,%2,%3};"
                        : "+f"(acc[mi][2*p][0]), "+f"(acc[mi][2*p][1]),
                          "+f"(acc[mi][2*p][2]), "+f"(acc[mi][2*p][3])
                        : "r"(a[mi][0]), "r"(a[mi][1]), "r"(a[mi][2]), "r"(a[mi][3]),
                          "r"(b0[0]), "r"(b0[1]));
                    asm volatile(
                        "mma.sync.aligned.m16n8k16.row.col.f32.bf16.bf16.f32 "
                        "{%0,%1,%2,%3}, {%4,%5,%6,%7}, {%8,%9}, {%0,%1,%2,%3};"
                        : "+f"(acc[mi][2*p+1][0]), "+f"(acc[mi][2*p+1][1]),
                          "+f"(acc[mi][2*p+1][2]), "+f"(acc[mi][2*p+1][3])
                        : "r"(a[mi][0]), "r"(a[mi][1]), "r"(a[mi][2]), "r"(a[mi][3]),
                          "r"(b1[0]), "r"(b1[1]));
                }
            }
        }
    }

    const int gq = lane >> 2;
    const int tg = lane & 3;

    if (bx < 4) {
#pragma unroll
        for (int mi = 0; mi < 4; mi++) {
            int r0 = by * 128 + warp_m * 64 + mi * 16 + gq;
            int r1 = r0 + 8;
#pragma unroll
            for (int ni = 0; ni < 8; ni++) {
                int col = bx * 128 + warp_n * 64 + ni * 8 + tg * 2;
                *(float2*)&g_T[(size_t)r0 * K_N + col] = make_float2(acc[mi][ni][0], acc[mi][ni][1]);
                *(float2*)&g_T[(size_t)r1 * K_N + col] = make_float2(acc[mi][ni][2], acc[mi][ni][3]);
            }
        }
    } else {
#pragma unroll
        for (int mi = 0; mi < 4; mi++) {
            int r0 = by * 128 + warp_m * 64 + mi * 16 + gq;
            int r1 = r0 + 8;
#pragma unroll
            for (int ni = 0; ni < 8; ni++) {
                int col = (bx - 4) * 128 + warp_n * 64 + ni * 8 + tg * 2;
                __nv_bfloat162 lo = __float22bfloat162_rn(make_float2(acc[mi][ni][0], acc[mi][ni][1]));
                __nv_bfloat162 hi = __float22bfloat162_rn(make_float2(acc[mi][ni][2], acc[mi][ni][3]));
                *(__nv_bfloat162*)&g_V[(size_t)r0 * 4096 + col] = lo;
                *(__nv_bfloat162*)&g_V[(size_t)r1 * 4096 + col] = hi;
            }
        }
    }
}

// ---------------- pC: reduce chunks, alpha, Cholesky -> packed Lp -----------
__global__ void pC(const float* __restrict__ scale_rho) {
    int k = blockIdx.x * 128 + threadIdx.x;
    if (k >= K_N) return;
    float buf[53];
    for (int i = 0; i < 53; i++) {
        float s = 0.0f;
        for (int c = 0; c < 4; c++) s += g_Sacc[(size_t)(k * 4 + c) * 56 + i];
        buf[i] = s;
    }
    float al[8];
#pragma unroll
    for (int j = 0; j < 8; j++) {
        float sp = softplusf(scale_rho[k * 8 + j]);
        al[j] = sp / fmaxf(sqrtf(buf[44 + j]), EPSC);
    }

    float Mm[8][8];
    int idx = 0;
    for (int i = 0; i < 8; i++)
        for (int j = 0; j <= i; j++)
            Mm[i][j] = al[i] * al[j] * buf[idx++] + (i == j ? 1.0f : 0.0f);
    for (int i = 0; i < 8; i++) {
        for (int j = 0; j <= i; j++) {
            float s = Mm[i][j];
            for (int p = 0; p < j; p++) s -= Mm[i][p] * Mm[j][p];
            if (i == j) Mm[i][i] = sqrtf(s);
            else        Mm[i][j] = s / Mm[j][j];
        }
    }
    float ld = 0.0f;
    for (int i = 0; i < 8; i++) ld += logf(Mm[i][i]);
    g_logdetM[k] = 2.0f * ld;
    g_mumu[k]    = buf[52];
    for (int j = 0; j < 8; j++) g_Lp[k * 48 + 36 + j] = buf[36 + j];

    float Li[8][8];
    for (int i = 0; i < 8; i++)
        for (int j = 0; j < 8; j++) Li[i][j] = 0.0f;
    for (int c = 0; c < 8; c++) {
        for (int i = c; i < 8; i++) {
            float s = (i == c) ? 1.0f : 0.0f;
            for (int p = c; p < i; p++) s -= Mm[i][p] * Li[p][c];
            Li[i][c] = s / Mm[i][i];
        }
    }
    idx = 0;
    for (int i = 0; i < 8; i++)
        for (int j = 0; j <= i; j++)
            g_Lp[k * 48 + idx++] = 0.70710678118654752f * Li[i][j] * al[j];
}

__global__ void k_init() { g_acc = 0.0; g_cnt = 0; }

// ---------------- per-k offset -> g_Lp[44] ----------------
__global__ void k_off(const float* __restrict__ pi_logits) {
    __shared__ float buf[512];
    int t = threadIdx.x;
    float v = pi_logits[t];
    buf[t] = v;
    __syncthreads();
    for (int s = 256; s > 0; s >>= 1) {
        if (t < s) buf[t] = fmaxf(buf[t], buf[t + s]);
        __syncthreads();
    }
    float mx = buf[0];
    __syncthreads();
    buf[t] = expf(v - mx);
    __syncthreads();
    for (int s = 256; s > 0; s >>= 1) {
        if (t < s) buf[t] += buf[t + s];
        __syncthreads();
    }
    float lse = logf(buf[0]) + mx;
    g_Lp[t * 48 + 44] = -0.5f * ((float)D_N * LOG2PI + g_logdetPsi + g_logdetM[t] + g_mumu[t])
                        + v - lse;
}

// ---------------- fused e1+e2: quad + logsumexp + NLL; last block -> out ----
__global__ void __launch_bounds__(256) k_e2(int b_base, float* out) {
    __shared__ float sL[64 * 49];
    int tid = threadIdx.x, warp = tid >> 5, lane = tid & 31;
    int b0 = b_base + blockIdx.x * 16 + warp * 2;
    int b1 = b0 + 1;
    const __nv_bfloat16* vr0 = g_V + (size_t)b0 * 4096;
    const __nv_bfloat16* vr1 = g_V + (size_t)b1 * 4096;
    const float* tr0 = g_T + (size_t)b0 * K_N;
    const float* tr1 = g_T + (size_t)b1 * K_N;

    float m0 = -1e30f, s0 = 0.0f, m1 = -1e30f, s1 = 0.0f;
    for (int ch = 0; ch < 8; ch++) {
        int k0 = ch * 64;
        for (int t = tid; t < 64 * 48; t += 256) {
            int kk = t / 48, c = t - kk * 48;
            sL[kk * 49 + c] = g_Lp[(size_t)(k0 + kk) * 48 + c];
        }
        __syncthreads();
#pragma unroll
        for (int half = 0; half < 2; half++) {
            int kl = half * 32 + lane;
            int k  = k0 + kl;
            const float* P = &sL[kl * 49];
#pragma unroll
            for (int bb = 0; bb < 2; bb++) {
                const __nv_bfloat16* vrow = bb ? vr1 : vr0;
                const float*          trow = bb ? tr1 : tr0;
                uint4 raw = *(const uint4*)(vrow + (size_t)k * 8);
                float v[8];
                {
                    float2 f0 = __bfloat1622float2(*(__nv_bfloat162*)&raw.x);
                    float2 f1 = __bfloat1622float2(*(__nv_bfloat162*)&raw.y);
                    float2 f2 = __bfloat1622float2(*(__nv_bfloat162*)&raw.z);
                    float2 f3 = __bfloat1622float2(*(__nv_bfloat162*)&raw.w);
                    v[0] = f0.x; v[1] = f0.y; v[2] = f1.x; v[3] = f1.y;
                    v[4] = f2.x; v[5] = f2.y; v[6] = f3.x; v[7] = f3.y;
                }
#pragma unroll
                for (int j = 0; j < 8; j++) v[j] -= P[36 + j];
                float q = 0.0f;
                int idx = 0;
#pragma unroll
                for (int i = 0; i < 8; i++) {
                    float y = 0.0f;
#pragma unroll
                    for (int j = 0; j <= i; j++) y += P[idx++] * v[j];
                    q += y * y;
                }
                float val = trow[k] + P[44] + q;
                if (bb == 0) {
                    if (val > m0) { s0 = s0 * __expf(m0 - val) + 1.0f; m0 = val; }
                    else          { s0 += __expf(val - m0); }
                } else {
                    if (val > m1) { s1 = s1 * __expf(m1 - val) + 1.0f; m1 = val; }
                    else          { s1 += __expf(val - m1); }
                }
            }
        }
        __syncthreads();
    }
#pragma unroll
    for (int o = 16; o; o >>= 1) {
        float mo = __shfl_xor_sync(0xffffffffu, m0, o);
        float so = __shfl_xor_sync(0xffffffffu, s0, o);
        float M = fmaxf(m0, mo);
        s0 = s0 * __expf(m0 - M) + so * __expf(mo - M);
        m0 = M;
        mo = __shfl_xor_sync(0xffffffffu, m1, o);
        so = __shfl_xor_sync(0xffffffffu, s1, o);
        M = fmaxf(m1, mo);
        s1 = s1 * __expf(m1 - M) + so * __expf(mo - M);
        m1 = M;
    }
    if (lane == 0) {
        float lp = (__logf(s0) + m0 - 0.5f * g_r[b0]) + (__logf(s1) + m1 - 0.5f * g_r[b1]);
        atomicAdd(&g_acc, (double)(-lp));
    }
    // last finishing block (across both e2 launches) writes the output
    __syncthreads();
    __shared__ int s_last;
    if (tid == 0) {
        __threadfence();
        s_last = (atomicAdd(&g_cnt, 1) == (B_N / 16) - 1) ? 1 : 0;
    }
    __syncthreads();
    if (s_last && tid == 0) {
        double a = atomicAdd(&g_acc, 0.0);
        out[0] = (float)(a * (1.0 / (double)B_N));
    }
}

// ---------------- launch: multi-stream fork/join + split GEMM/e2 ------------
extern "C" void kernel_launch(void* const* d_in, const int* in_sizes, int n_in,
                              void* d_out, int out_size) {
    const float* x         = (const float*)d_in[0];
    const float* mu        = (const float*)d_in[1];
    const float* dir_raw   = (const float*)d_in[2];
    const float* scale_rho = (const float*)d_in[3];
    const float* psi_rho   = (const float*)d_in[4];
    const float* pi_logits = (const float*)d_in[5];
    float* out = (float*)d_out;

    static cudaStream_t s_aux = nullptr;
    static cudaEvent_t ev_fork1, ev_join1, ev_fork2, ev_join2, ev_g1, ev_e1;
    if (!s_aux) {
        cudaStreamCreateWithFlags(&s_aux, cudaStreamNonBlocking);
        cudaEventCreateWithFlags(&ev_fork1, cudaEventDisableTiming);
        cudaEventCreateWithFlags(&ev_join1, cudaEventDisableTiming);
        cudaEventCreateWithFlags(&ev_fork2, cudaEventDisableTiming);
        cudaEventCreateWithFlags(&ev_join2, cudaEventDisableTiming);
        cudaEventCreateWithFlags(&ev_g1,    cudaEventDisableTiming);
        cudaEventCreateWithFlags(&ev_e1,    cudaEventDisableTiming);
        cudaFuncSetAttribute(k_mma_gemm, cudaFuncAttributeMaxDynamicSharedMemorySize, GEMM_SMEM);
    }

    // main: psi, then fork
    k_psi<<<1, 1024>>>(psi_rho);
    cudaEventRecord(ev_fork1, 0);
    cudaStreamWaitEvent(s_aux, ev_fork1, 0);

    // aux: X conversion (|| with pB on main)
    k_cvt<<<B_N / 8, 256, 0, s_aux>>>(x);
    cudaEventRecord(ev_join1, s_aux);

    // main: W construction
    pB<<<dim3(4, K_N), 256>>>(dir_raw, mu);

    // fork 2: pC/init/off chain on aux (|| with GEMM on main)
    cudaEventRecord(ev_fork2, 0);
    cudaStreamWaitEvent(s_aux, ev_fork2, 0);   // aux ordered after k_cvt AND pB
    pC<<<4, 128, 0, s_aux>>>(scale_rho);
    k_init<<<1, 1, 0, s_aux>>>();
    k_off<<<1, 512, 0, s_aux>>>(pi_logits);
    cudaEventRecord(ev_join2, s_aux);

    // main: GEMM half 1 (rows 0..4095); needs g_XB (aux) + g_WB (pB)
    cudaStreamWaitEvent(0, ev_join1, 0);
    dim3 gg(36, 32);
    k_mma_gemm<<<gg, 128, GEMM_SMEM>>>(0);
    cudaEventRecord(ev_g1, 0);

    // main: GEMM half 2 (rows 4096..8191)
    k_mma_gemm<<<gg, 128, GEMM_SMEM>>>(32);

    // aux: e2 half 1 overlaps GEMM half 2 (aux already carries Lp chain order)
    cudaStreamWaitEvent(s_aux, ev_g1, 0);
    k_e2<<<B_N / 32, 256, 0, s_aux>>>(0, out);
    cudaEventRecord(ev_e1, s_aux);

    // main: e2 half 2 (after GEMM2; needs Lp chain too), then join aux back
    cudaStreamWaitEvent(0, ev_join2, 0);
    k_e2<<<B_N / 32, 256>>>(B_N / 2, out);
    cudaStreamWaitEvent(0, ev_e1, 0);
}